// round 5
// baseline (speedup 1.0000x reference)
#include <cuda_runtime.h>
#include <math.h>

#define BB  64
#define HH  2048
#define GG  8192
#define CCC 512
#define RRR 100

// ---- device scratch (no allocations allowed) ----
__device__ float g_h1[BB*HH];
__device__ float g_h [BB*HH];
__device__ float g_pre[BB*GG];
__device__ float g_mask[BB*GG];
__device__ float g_S[BB];
__device__ float g_sparse[BB*GG];
__device__ float g_state[BB*CCC];
__device__ float g_sep[BB*CCC];
__device__ float g_comp[BB*CCC];
__device__ float g_rec[BB*CCC];
__device__ float g_itch[BB*256];
__device__ float g_ic[BB];
__device__ float g_weffT[CCC*CCC];
__device__ float g_oh[BB*HH];
__device__ float g_ps[1<<23];   // split-K partials (32 MB)

// ---- threefry2x32, JAX partitionable: counter (0, idx), out = x0^x1 ----
__device__ __forceinline__ unsigned tf_rotl(unsigned x, int d){ return (x<<d)|(x>>(32-d)); }
__device__ __forceinline__ bool tf_keep(int idx){
    const unsigned ks0=0u, ks1=42u, ks2=0x1BD11BDAu^0u^42u;
    unsigned x0 = 0u + ks0;
    unsigned x1 = (unsigned)idx + ks1;
#define TFR(r) { x0+=x1; x1=tf_rotl(x1,(r)); x1^=x0; }
    TFR(13) TFR(15) TFR(26) TFR(6)  x0+=ks1; x1+=ks2+1u;
    TFR(17) TFR(29) TFR(16) TFR(24) x0+=ks2; x1+=ks0+2u;
    TFR(13) TFR(15) TFR(26) TFR(6)  x0+=ks0; x1+=ks1+3u;
    TFR(17) TFR(29) TFR(16) TFR(24) x0+=ks1; x1+=ks2+4u;
    TFR(13) TFR(15) TFR(26) TFR(6)  x0+=ks2; x1+=ks0+5u;
#undef TFR
    unsigned bits = x0 ^ x1;
    float u = __uint_as_float((bits>>9)|0x3f800000u) - 1.0f;
    return u > 0.1f;
}

// packed f32x2 FMA: acc = a*b + acc (each operand holds 2 floats)
#define FMA2(accv, av, bv) \
    asm("fma.rn.f32x2 %0, %1, %2, %0;" : "+l"(accv) : "l"(av), "l"(bv))

// ---- column-per-thread split-K GEMM ----
// partial[b, n] = sum_{k in [kb,kb+Kc)} X[b,k] * W[n,k]
// grid.x = N/256, grid.y = K/Kc, grid.z = weight batch. 256 threads.
// Thread owns column n = bx*256+tid and ALL 64 rows (32 f32x2 accumulators).
// W is streamed from global through registers (per-thread contiguous rows);
// X tile staged in smem k-major, read as broadcast row-pair f32x2 operands.
__global__ __launch_bounds__(256,2) void gemmC(
    const float* __restrict__ Xg, const float* __restrict__ Wg,
    float* __restrict__ ps, int K, int Kc, int N, int wzStride)
{
    __shared__ float Xs[32][72];   // [kk][row]; 72-float stride: aligned + STS conflict-free
    const int tid = threadIdx.x;
    const int n   = blockIdx.x*256 + tid;
    const int kb  = blockIdx.y*Kc;
    const float* Wrow = Wg + (size_t)blockIdx.z*(size_t)wzStride + (size_t)n*K;
    float* outp = ps + (size_t)(blockIdx.z*gridDim.y + blockIdx.y)*(size_t)(BB*N);

    unsigned long long acc[32];
#pragma unroll
    for (int i=0;i<32;i++) acc[i] = 0ull;

    const int r  = tid & 63;       // staging: row
    const int kq = tid >> 6;       // staging: k-octet 0..3

    for (int k0 = kb; k0 < kb + Kc; k0 += 32) {
        __syncthreads();
        {
            const float* xp = Xg + (size_t)r*K + k0 + kq*8;
            float4 a0 = *(const float4*)xp;
            float4 a1 = *(const float4*)(xp+4);
            int kbase = kq*8;
            Xs[kbase+0][r]=a0.x; Xs[kbase+1][r]=a0.y; Xs[kbase+2][r]=a0.z; Xs[kbase+3][r]=a0.w;
            Xs[kbase+4][r]=a1.x; Xs[kbase+5][r]=a1.y; Xs[kbase+6][r]=a1.z; Xs[kbase+7][r]=a1.w;
        }
        __syncthreads();

        const float* wp = Wrow + k0;
#pragma unroll
        for (int g=0; g<8; ++g) {
            float4 wv = *(const float4*)(wp + g*4);
#pragma unroll
            for (int j=0; j<4; ++j) {
                int k = g*4 + j;
                float w = (j==0)?wv.x:(j==1)?wv.y:(j==2)?wv.z:wv.w;
                unsigned long long bb;
                asm("mov.b64 %0, {%1, %1};" : "=l"(bb) : "f"(w));
                const ulonglong2* ap = (const ulonglong2*)(&Xs[k][0]);
#pragma unroll
                for (int m=0; m<16; ++m) {
                    ulonglong2 av = ap[m];
                    FMA2(acc[2*m],   av.x, bb);
                    FMA2(acc[2*m+1], av.y, bb);
                }
            }
        }
    }

#pragma unroll
    for (int i=0;i<32;i++){
        float lo, hi;
        asm("mov.b64 {%0, %1}, %2;" : "=f"(lo), "=f"(hi) : "l"(acc[i]));
        outp[(size_t)(2*i  )*N + n] = lo;
        outp[(size_t)(2*i+1)*N + n] = hi;
    }
}

// ---- split-K reduce + epilogue ----
#define M_NONE 0
#define M_RELU 1
#define M_MASK 2
#define M_MF   3
#define M_RECB 4
__global__ void combine_k(const float* __restrict__ ps, int KS, int BN, int N,
                          const float* __restrict__ bias, const float* __restrict__ extra,
                          float* __restrict__ out, int mode)
{
    int idx = blockIdx.x*256 + threadIdx.x;
    if (idx >= BN) return;
    float z = 0.0f;
    for (int s=0;s<KS;s++) z += ps[(size_t)s*BN + idx];
    int n = idx % N;
    float v;
    if (mode == M_RECB) { z += extra[idx]; v = fmaxf(z,0.0f); }
    else {
        if (bias) z += bias[n];
        if (mode==M_NONE)      v = z;
        else if (mode==M_RELU) v = fmaxf(z,0.0f);
        else if (mode==M_MASK) { float g = 1.0f/(1.0f+expf(-z)); v = (g>0.1f)?1.0f:0.0f; }
        else { float p = z*extra[n]; v = tf_keep(idx)?p:0.0f; }   // M_MF
    }
    out[idx] = v;
}

// 3-branch running pairwise average: sig=0 -> tanh*0.8, sig=1 -> sigmoid*0.6
__global__ void combine3_k(const float* __restrict__ ps, int KS,
                           const float* __restrict__ bias, float* __restrict__ out, int sig)
{
    int idx = blockIdx.x*256 + threadIdx.x;
    if (idx >= BB*CCC) return;
    int n = idx & (CCC-1);
    float z[3];
#pragma unroll
    for (int br=0;br<3;br++){
        float a = 0.0f;
        for (int s=0;s<KS;s++) a += ps[(size_t)(br*KS+s)*(BB*CCC) + idx];
        z[br] = a + bias[br*CCC + n];
    }
    float v;
    if (!sig){
        v = tanhf(z[0])*0.8f;
        v = (v + tanhf(z[1])*0.8f)*0.5f;
        v = (v + tanhf(z[2])*0.8f)*0.5f;
    } else {
        v = 0.6f/(1.0f+expf(-z[0]));
        v = (v + 0.6f/(1.0f+expf(-z[1])))*0.5f;
        v = (v + 0.6f/(1.0f+expf(-z[2])))*0.5f;
    }
    out[idx] = v;
}

__global__ void mask_stats_k()
{
    __shared__ float red[256];
    int b = blockIdx.x, tid = threadIdx.x;
    float s = 0.0f;
    for (int j=tid;j<GG;j+=256) s += g_mask[(size_t)b*GG + j];
    red[tid]=s; __syncthreads();
    for (int off=128;off;off>>=1){ if(tid<off) red[tid]+=red[tid+off]; __syncthreads(); }
    if (tid==0) g_S[b]=red[0];
}

// inhibition + sparse + LayerNorm; one block per batch row
__global__ void sparse_ln_k(const float* __restrict__ lng, const float* __restrict__ lnb)
{
    __shared__ float sv[GG];
    __shared__ float red[256];
    int b = blockIdx.x, tid = threadIdx.x;
    float tot = 0.0f;
    for (int i=0;i<BB;i++) tot += g_S[i];
    bool anyb = tot > 0.0f;
    float Sb = g_S[b];

    float lsum = 0.0f;
    for (int j=tid;j<GG;j+=256){
        float m = g_mask[(size_t)b*GG + j];
        float p = g_pre [(size_t)b*GG + j];
        if (anyb) p -= 0.1f*(Sb - m);
        float s = p*m;
        sv[j]=s; lsum+=s;
    }
    red[tid]=lsum; __syncthreads();
    for (int off=128;off;off>>=1){ if(tid<off) red[tid]+=red[tid+off]; __syncthreads(); }
    float mu = red[0]/(float)GG; __syncthreads();

    float lsq = 0.0f;
    for (int j=tid;j<GG;j+=256){ float d=sv[j]-mu; lsq+=d*d; }
    red[tid]=lsq; __syncthreads();
    for (int off=128;off;off>>=1){ if(tid<off) red[tid]+=red[tid+off]; __syncthreads(); }
    float rstd = 1.0f/sqrtf(red[0]/(float)GG + 1e-5f);

    for (int j=tid;j<GG;j+=256)
        g_sparse[(size_t)b*GG + j] = (sv[j]-mu)*rstd*lng[j] + lnb[j];
}

// WeffT[h,d] = sum_c strength_c * recW[c,d,h]   (float4-vectorized over gid)
__global__ void build_weff_k(const float* __restrict__ recW)
{
    int g4 = blockIdx.x*256 + threadIdx.x;     // over (CCC*CCC)/4
    if (g4 >= (CCC*CCC)/4) return;
    float4 acc = make_float4(0.f,0.f,0.f,0.f);
    for (int c=0;c<RRR;c++){
        float s = 1.0f/(1.0f+0.1f*(float)c);
        float4 v = *(const float4*)(recW + (size_t)c*CCC*CCC + g4*4);
        acc.x += s*v.x; acc.y += s*v.y; acc.z += s*v.z; acc.w += s*v.w;
    }
    int gid = g4*4;
#pragma unroll
    for (int j=0;j<4;j++){
        int d = (gid+j) >> 9, h = (gid+j) & (CCC-1);
        g_weffT[(size_t)h*CCC + d] = (&acc.x)[j];
    }
}

__global__ void itc2_k(const float* __restrict__ w2, const float* __restrict__ b2)
{
    __shared__ float red[256];
    int b = blockIdx.x, tid = threadIdx.x;
    red[tid] = g_itch[b*256+tid]*w2[tid]; __syncthreads();
    for (int off=128;off;off>>=1){ if(tid<off) red[tid]+=red[tid+off]; __syncthreads(); }
    if (tid==0) g_ic[b] = 1.0f/(1.0f+expf(-(red[0]+b2[0])));
}

__global__ void update_k()
{
    int idx = blockIdx.x*256 + threadIdx.x;
    if (idx >= BB*CCC) return;
    float ic = g_ic[idx>>9];
    g_state[idx] = (1.0f-ic)*g_state[idx] + ic*g_rec[idx];
}

extern "C" void kernel_launch(void* const* d_in, const int* in_sizes, int n_in,
                              void* d_out, int out_size)
{
    const float* x1    = (const float*)d_in[0];
    const float* ipW1  = (const float*)d_in[1];
    const float* ipb1  = (const float*)d_in[2];
    const float* ipW2  = (const float*)d_in[3];
    const float* ipb2  = (const float*)d_in[4];
    const float* encW  = (const float*)d_in[5];
    const float* encb  = (const float*)d_in[6];
    const float* gateW = (const float*)d_in[7];
    const float* gateb = (const float*)d_in[8];
    const float* ln_g  = (const float*)d_in[9];
    const float* ln_b  = (const float*)d_in[10];
    /* d_in[11] lateral: ones-eye, handled analytically */
    const float* mfW   = (const float*)d_in[12];
    const float* mfb   = (const float*)d_in[13];
    const float* mf_cs = (const float*)d_in[14];
    const float* recW  = (const float*)d_in[15];
    const float* recb  = (const float*)d_in[16];
    const float* sepW  = (const float*)d_in[17];
    const float* sepb  = (const float*)d_in[18];
    const float* compW = (const float*)d_in[19];
    const float* compb = (const float*)d_in[20];
    const float* itcW1 = (const float*)d_in[21];
    const float* itcb1 = (const float*)d_in[22];
    const float* itcW2 = (const float*)d_in[23];
    const float* itcb2 = (const float*)d_in[24];
    const float* opW1  = (const float*)d_in[25];
    const float* opb1  = (const float*)d_in[26];
    const float* opW2  = (const float*)d_in[27];
    const float* opb2  = (const float*)d_in[28];

    float *p_h1,*p_h,*p_pre,*p_mask,*p_sparse,*p_state,*p_sep,*p_comp,*p_rec,*p_itch,*p_weffT,*p_oh,*p_ps;
    cudaGetSymbolAddress((void**)&p_h1, g_h1);
    cudaGetSymbolAddress((void**)&p_h,  g_h);
    cudaGetSymbolAddress((void**)&p_pre, g_pre);
    cudaGetSymbolAddress((void**)&p_mask, g_mask);
    cudaGetSymbolAddress((void**)&p_sparse, g_sparse);
    cudaGetSymbolAddress((void**)&p_state, g_state);
    cudaGetSymbolAddress((void**)&p_sep, g_sep);
    cudaGetSymbolAddress((void**)&p_comp, g_comp);
    cudaGetSymbolAddress((void**)&p_rec, g_rec);
    cudaGetSymbolAddress((void**)&p_itch, g_itch);
    cudaGetSymbolAddress((void**)&p_weffT, g_weffT);
    cudaGetSymbolAddress((void**)&p_oh, g_oh);
    cudaGetSymbolAddress((void**)&p_ps, g_ps);

    dim3 t(256);

    // Weff (used in all 3 iterations)
    build_weff_k<<<256, t>>>(recW);

    // input projection
    gemmC<<<dim3(8,16,1), t>>>(x1,  ipW1, p_ps, 1024, 64, 2048, 0);
    combine_k<<<512, t>>>(p_ps, 16, BB*2048, 2048, ipb1, nullptr, p_h1, M_RELU);
    gemmC<<<dim3(8,16,1), t>>>(p_h1, ipW2, p_ps, 2048, 128, 2048, 0);
    combine_k<<<512, t>>>(p_ps, 16, BB*2048, 2048, ipb2, nullptr, p_h, M_NONE);

    // granule: pre + gate mask
    gemmC<<<dim3(32,8,1), t>>>(p_h, encW, p_ps, 2048, 256, 8192, 0);
    combine_k<<<2048, t>>>(p_ps, 8, BB*8192, 8192, encb, nullptr, p_pre, M_NONE);
    gemmC<<<dim3(32,16,1), t>>>(p_pre, gateW, p_ps, 8192, 512, 8192, 0);
    combine_k<<<2048, t>>>(p_ps, 16, BB*8192, 8192, gateb, nullptr, p_mask, M_MASK);

    // inhibition + sparse + LN
    mask_stats_k<<<64, t>>>();
    sparse_ln_k<<<64, t>>>(ln_g, ln_b);

    // mossy fiber + dropout
    gemmC<<<dim3(2,64,1), t>>>(p_sparse, mfW, p_ps, 8192, 128, 512, 0);
    combine_k<<<128, t>>>(p_ps, 64, BB*512, 512, mfb, mf_cs, p_state, M_MF);

    // CA3 recurrence, 3 iterations
    for (int it=0; it<3; it++) {
        gemmC<<<dim3(2,16,3), t>>>(p_state, sepW, p_ps, 512, 32, 512, CCC*CCC);
        combine3_k<<<128, t>>>(p_ps, 16, sepb, p_sep, 0);
        gemmC<<<dim3(2,16,3), t>>>(p_sep, compW, p_ps, 512, 32, 512, CCC*CCC);
        combine3_k<<<128, t>>>(p_ps, 16, compb, p_comp, 1);
        gemmC<<<dim3(2,16,1), t>>>(p_comp, p_weffT, p_ps, 512, 32, 512, 0);
        combine_k<<<128, t>>>(p_ps, 16, BB*512, 512, nullptr, recb, p_rec, M_RECB);
        gemmC<<<dim3(1,16,1), t>>>(p_rec, itcW1, p_ps, 512, 32, 256, 0);
        combine_k<<<64, t>>>(p_ps, 16, BB*256, 256, itcb1, nullptr, p_itch, M_RELU);
        itc2_k<<<64, t>>>(itcW2, itcb2);
        update_k<<<128, t>>>();
    }

    // output projection
    gemmC<<<dim3(8,8,1), t>>>(p_state, opW1, p_ps, 512, 64, 2048, 0);
    combine_k<<<512, t>>>(p_ps, 8, BB*2048, 2048, opb1, nullptr, p_oh, M_RELU);
    gemmC<<<dim3(4,32,1), t>>>(p_oh, opW2, p_ps, 2048, 64, 1024, 0);
    combine_k<<<256, t>>>(p_ps, 32, BB*1024, 1024, opb2, nullptr, (float*)d_out, M_NONE);
}

// round 6
// speedup vs baseline: 1.2545x; 1.2545x over previous
#include <cuda_runtime.h>
#include <math.h>

#define BB  64
#define HH  2048
#define GG  8192
#define CCC 512
#define RRR 100

// ---- device scratch (no allocations allowed) ----
__device__ float g_h1[BB*HH];
__device__ float g_h [BB*HH];
__device__ float g_pre[BB*GG];
__device__ float g_mask[BB*GG];
__device__ float g_S[BB];
__device__ float g_sparse[BB*GG];
__device__ float g_state[BB*CCC];
__device__ float g_sep[BB*CCC];
__device__ float g_comp[BB*CCC];
__device__ float g_rec[BB*CCC];
__device__ float g_itch[BB*256];
__device__ float g_ic[BB];
__device__ float g_weffT[CCC*CCC];
__device__ float g_oh[BB*HH];
__device__ float g_ps[1<<23];   // split-K partials (32 MB)

// ---- threefry2x32, JAX partitionable: counter (0, idx), out = x0^x1 ----
__device__ __forceinline__ unsigned tf_rotl(unsigned x, int d){ return (x<<d)|(x>>(32-d)); }
__device__ __forceinline__ bool tf_keep(int idx){
    const unsigned ks0=0u, ks1=42u, ks2=0x1BD11BDAu^0u^42u;
    unsigned x0 = 0u + ks0;
    unsigned x1 = (unsigned)idx + ks1;
#define TFR(r) { x0+=x1; x1=tf_rotl(x1,(r)); x1^=x0; }
    TFR(13) TFR(15) TFR(26) TFR(6)  x0+=ks1; x1+=ks2+1u;
    TFR(17) TFR(29) TFR(16) TFR(24) x0+=ks2; x1+=ks0+2u;
    TFR(13) TFR(15) TFR(26) TFR(6)  x0+=ks0; x1+=ks1+3u;
    TFR(17) TFR(29) TFR(16) TFR(24) x0+=ks1; x1+=ks2+4u;
    TFR(13) TFR(15) TFR(26) TFR(6)  x0+=ks2; x1+=ks0+5u;
#undef TFR
    unsigned bits = x0 ^ x1;
    float u = __uint_as_float((bits>>9)|0x3f800000u) - 1.0f;
    return u > 0.1f;
}

// packed f32x2 FMA: acc = a*b + acc
#define FMA2(accv, av, bv) \
    asm("fma.rn.f32x2 %0, %1, %2, %0;" : "+l"(accv) : "l"(av), "l"(bv))
#define DUP2(dst, w) \
    asm("mov.b64 %0, {%1, %1};" : "=l"(dst) : "f"(w))

// ---- split-K GEMM: partial[b,n] = sum_{k in seg} X[b,k]*W[n,k] ----
// 64x128 tile, 256 threads, 8x4 micro-tile in f32x2 row-pairs.
// Chunk K=16, k-major smem, register-prefetch double buffering.
__global__ __launch_bounds__(256,3) void gemm64(
    const float* __restrict__ Xg, const float* __restrict__ Wg,
    float* __restrict__ ps, int K, int Kc, int N, int wzStride)
{
    __shared__ float Xs[16][72];
    __shared__ float Ws[16][136];
    const int tid = threadIdx.x;
    const int n0  = blockIdx.x * 128;
    const int kb  = blockIdx.y * Kc;
    const float* W = Wg + (size_t)blockIdx.z*(size_t)wzStride;
    float* outp = ps + (size_t)(blockIdx.z*gridDim.y + blockIdx.y)*(size_t)(BB*N);

    const int ty = tid >> 5;        // 8 row-groups of 8 rows
    const int tx = tid & 31;        // 32 col-groups of 4 cols

    // staging maps
    const int xr = tid & 63,  xkg = tid >> 6;   // X: row, k-quad (4 k each)
    const int wc = tid & 127, wkg = tid >> 7;   // W: col, k-oct (8 k each)

    unsigned long long acc[4][4];
#pragma unroll
    for (int p=0;p<4;p++)
#pragma unroll
        for (int j=0;j<4;j++) acc[p][j]=0ull;

    // prefetch first chunk
    float4 xa  = *(const float4*)(Xg + (size_t)xr*K + kb + xkg*4);
    float4 wa0 = *(const float4*)(W + (size_t)(n0+wc)*K + kb + wkg*8);
    float4 wa1 = *(const float4*)(W + (size_t)(n0+wc)*K + kb + wkg*8 + 4);

    for (int k0 = kb; k0 < kb + Kc; k0 += 16) {
        Xs[xkg*4+0][xr]=xa.x; Xs[xkg*4+1][xr]=xa.y; Xs[xkg*4+2][xr]=xa.z; Xs[xkg*4+3][xr]=xa.w;
        Ws[wkg*8+0][wc]=wa0.x; Ws[wkg*8+1][wc]=wa0.y; Ws[wkg*8+2][wc]=wa0.z; Ws[wkg*8+3][wc]=wa0.w;
        Ws[wkg*8+4][wc]=wa1.x; Ws[wkg*8+5][wc]=wa1.y; Ws[wkg*8+6][wc]=wa1.z; Ws[wkg*8+7][wc]=wa1.w;
        __syncthreads();

        int kn = k0 + 16;
        if (kn < kb + Kc) {
            xa  = *(const float4*)(Xg + (size_t)xr*K + kn + xkg*4);
            wa0 = *(const float4*)(W + (size_t)(n0+wc)*K + kn + wkg*8);
            wa1 = *(const float4*)(W + (size_t)(n0+wc)*K + kn + wkg*8 + 4);
        }

#pragma unroll
        for (int kk=0; kk<16; ++kk) {
            ulonglong2 a01 = *(const ulonglong2*)&Xs[kk][ty*8];     // rows 0..3 (2 f32x2)
            ulonglong2 a23 = *(const ulonglong2*)&Xs[kk][ty*8+4];   // rows 4..7
            float4 wv = *(const float4*)&Ws[kk][tx*4];
            unsigned long long b0,b1,b2,b3;
            DUP2(b0,wv.x); DUP2(b1,wv.y); DUP2(b2,wv.z); DUP2(b3,wv.w);
            FMA2(acc[0][0],a01.x,b0); FMA2(acc[0][1],a01.x,b1); FMA2(acc[0][2],a01.x,b2); FMA2(acc[0][3],a01.x,b3);
            FMA2(acc[1][0],a01.y,b0); FMA2(acc[1][1],a01.y,b1); FMA2(acc[1][2],a01.y,b2); FMA2(acc[1][3],a01.y,b3);
            FMA2(acc[2][0],a23.x,b0); FMA2(acc[2][1],a23.x,b1); FMA2(acc[2][2],a23.x,b2); FMA2(acc[2][3],a23.x,b3);
            FMA2(acc[3][0],a23.y,b0); FMA2(acc[3][1],a23.y,b1); FMA2(acc[3][2],a23.y,b2); FMA2(acc[3][3],a23.y,b3);
        }
        __syncthreads();
    }

    // epilogue: unpack row-pairs, vectorized float4 stores
#pragma unroll
    for (int p=0;p<4;p++){
        float lo[4], hi[4];
#pragma unroll
        for (int j=0;j<4;j++)
            asm("mov.b64 {%0, %1}, %2;" : "=f"(lo[j]), "=f"(hi[j]) : "l"(acc[p][j]));
        int r0 = ty*8 + 2*p;
        *(float4*)(outp + (size_t)r0    *N + n0 + tx*4) = make_float4(lo[0],lo[1],lo[2],lo[3]);
        *(float4*)(outp + (size_t)(r0+1)*N + n0 + tx*4) = make_float4(hi[0],hi[1],hi[2],hi[3]);
    }
}

// ---- split-K reduce + epilogue ----
#define M_NONE 0
#define M_RELU 1
#define M_MASK 2
#define M_MF   3
#define M_RECB 4
__global__ void combine_k(const float* __restrict__ ps, int KS, int BN, int N,
                          const float* __restrict__ bias, const float* __restrict__ extra,
                          float* __restrict__ out, int mode)
{
    int idx = blockIdx.x*256 + threadIdx.x;
    if (idx >= BN) return;
    float z = 0.0f;
    for (int s=0;s<KS;s++) z += ps[(size_t)s*BN + idx];
    int n = idx % N;
    float v;
    if (mode == M_RECB) { z += extra[idx]; v = fmaxf(z,0.0f); }
    else {
        if (bias) z += bias[n];
        if (mode==M_NONE)      v = z;
        else if (mode==M_RELU) v = fmaxf(z,0.0f);
        else if (mode==M_MASK) { float g = 1.0f/(1.0f+expf(-z)); v = (g>0.1f)?1.0f:0.0f; }
        else { float p = z*extra[n]; v = tf_keep(idx)?p:0.0f; }   // M_MF
    }
    out[idx] = v;
}

// 3-branch running pairwise average: sig=0 -> tanh*0.8, sig=1 -> sigmoid*0.6
__global__ void combine3_k(const float* __restrict__ ps, int KS,
                           const float* __restrict__ bias, float* __restrict__ out, int sig)
{
    int idx = blockIdx.x*256 + threadIdx.x;
    if (idx >= BB*CCC) return;
    int n = idx & (CCC-1);
    float z[3];
#pragma unroll
    for (int br=0;br<3;br++){
        float a = 0.0f;
        for (int s=0;s<KS;s++) a += ps[(size_t)(br*KS+s)*(BB*CCC) + idx];
        z[br] = a + bias[br*CCC + n];
    }
    float v;
    if (!sig){
        v = tanhf(z[0])*0.8f;
        v = (v + tanhf(z[1])*0.8f)*0.5f;
        v = (v + tanhf(z[2])*0.8f)*0.5f;
    } else {
        v = 0.6f/(1.0f+expf(-z[0]));
        v = (v + 0.6f/(1.0f+expf(-z[1])))*0.5f;
        v = (v + 0.6f/(1.0f+expf(-z[2])))*0.5f;
    }
    out[idx] = v;
}

__global__ void mask_stats_k()
{
    __shared__ float red[256];
    int b = blockIdx.x, tid = threadIdx.x;
    float s = 0.0f;
    for (int j=tid;j<GG;j+=256) s += g_mask[(size_t)b*GG + j];
    red[tid]=s; __syncthreads();
    for (int off=128;off;off>>=1){ if(tid<off) red[tid]+=red[tid+off]; __syncthreads(); }
    if (tid==0) g_S[b]=red[0];
}

// inhibition + sparse + LayerNorm; one block per batch row
__global__ void sparse_ln_k(const float* __restrict__ lng, const float* __restrict__ lnb)
{
    __shared__ float sv[GG];
    __shared__ float red[256];
    int b = blockIdx.x, tid = threadIdx.x;
    float tot = 0.0f;
    for (int i=0;i<BB;i++) tot += g_S[i];
    bool anyb = tot > 0.0f;
    float Sb = g_S[b];

    float lsum = 0.0f;
    for (int j=tid;j<GG;j+=256){
        float m = g_mask[(size_t)b*GG + j];
        float p = g_pre [(size_t)b*GG + j];
        if (anyb) p -= 0.1f*(Sb - m);
        float s = p*m;
        sv[j]=s; lsum+=s;
    }
    red[tid]=lsum; __syncthreads();
    for (int off=128;off;off>>=1){ if(tid<off) red[tid]+=red[tid+off]; __syncthreads(); }
    float mu = red[0]/(float)GG; __syncthreads();

    float lsq = 0.0f;
    for (int j=tid;j<GG;j+=256){ float d=sv[j]-mu; lsq+=d*d; }
    red[tid]=lsq; __syncthreads();
    for (int off=128;off;off>>=1){ if(tid<off) red[tid]+=red[tid+off]; __syncthreads(); }
    float rstd = 1.0f/sqrtf(red[0]/(float)GG + 1e-5f);

    for (int j=tid;j<GG;j+=256)
        g_sparse[(size_t)b*GG + j] = (sv[j]-mu)*rstd*lng[j] + lnb[j];
}

// WeffT[h,d] = sum_c strength_c * recW[c,d,h]   (float4-vectorized)
__global__ void build_weff_k(const float* __restrict__ recW)
{
    int g4 = blockIdx.x*256 + threadIdx.x;
    if (g4 >= (CCC*CCC)/4) return;
    float4 acc = make_float4(0.f,0.f,0.f,0.f);
    for (int c=0;c<RRR;c++){
        float s = 1.0f/(1.0f+0.1f*(float)c);
        float4 v = *(const float4*)(recW + (size_t)c*CCC*CCC + g4*4);
        acc.x += s*v.x; acc.y += s*v.y; acc.z += s*v.z; acc.w += s*v.w;
    }
    int gid = g4*4;
#pragma unroll
    for (int j=0;j<4;j++){
        int d = (gid+j) >> 9, h = (gid+j) & (CCC-1);
        g_weffT[(size_t)h*CCC + d] = (&acc.x)[j];
    }
}

__global__ void itc2_k(const float* __restrict__ w2, const float* __restrict__ b2)
{
    __shared__ float red[256];
    int b = blockIdx.x, tid = threadIdx.x;
    red[tid] = g_itch[b*256+tid]*w2[tid]; __syncthreads();
    for (int off=128;off;off>>=1){ if(tid<off) red[tid]+=red[tid+off]; __syncthreads(); }
    if (tid==0) g_ic[b] = 1.0f/(1.0f+expf(-(red[0]+b2[0])));
}

__global__ void update_k()
{
    int idx = blockIdx.x*256 + threadIdx.x;
    if (idx >= BB*CCC) return;
    float ic = g_ic[idx>>9];
    g_state[idx] = (1.0f-ic)*g_state[idx] + ic*g_rec[idx];
}

extern "C" void kernel_launch(void* const* d_in, const int* in_sizes, int n_in,
                              void* d_out, int out_size)
{
    const float* x1    = (const float*)d_in[0];
    const float* ipW1  = (const float*)d_in[1];
    const float* ipb1  = (const float*)d_in[2];
    const float* ipW2  = (const float*)d_in[3];
    const float* ipb2  = (const float*)d_in[4];
    const float* encW  = (const float*)d_in[5];
    const float* encb  = (const float*)d_in[6];
    const float* gateW = (const float*)d_in[7];
    const float* gateb = (const float*)d_in[8];
    const float* ln_g  = (const float*)d_in[9];
    const float* ln_b  = (const float*)d_in[10];
    /* d_in[11] lateral: ones-eye, handled analytically */
    const float* mfW   = (const float*)d_in[12];
    const float* mfb   = (const float*)d_in[13];
    const float* mf_cs = (const float*)d_in[14];
    const float* recW  = (const float*)d_in[15];
    const float* recb  = (const float*)d_in[16];
    const float* sepW  = (const float*)d_in[17];
    const float* sepb  = (const float*)d_in[18];
    const float* compW = (const float*)d_in[19];
    const float* compb = (const float*)d_in[20];
    const float* itcW1 = (const float*)d_in[21];
    const float* itcb1 = (const float*)d_in[22];
    const float* itcW2 = (const float*)d_in[23];
    const float* itcb2 = (const float*)d_in[24];
    const float* opW1  = (const float*)d_in[25];
    const float* opb1  = (const float*)d_in[26];
    const float* opW2  = (const float*)d_in[27];
    const float* opb2  = (const float*)d_in[28];

    float *p_h1,*p_h,*p_pre,*p_mask,*p_sparse,*p_state,*p_sep,*p_comp,*p_rec,*p_itch,*p_weffT,*p_oh,*p_ps;
    cudaGetSymbolAddress((void**)&p_h1, g_h1);
    cudaGetSymbolAddress((void**)&p_h,  g_h);
    cudaGetSymbolAddress((void**)&p_pre, g_pre);
    cudaGetSymbolAddress((void**)&p_mask, g_mask);
    cudaGetSymbolAddress((void**)&p_sparse, g_sparse);
    cudaGetSymbolAddress((void**)&p_state, g_state);
    cudaGetSymbolAddress((void**)&p_sep, g_sep);
    cudaGetSymbolAddress((void**)&p_comp, g_comp);
    cudaGetSymbolAddress((void**)&p_rec, g_rec);
    cudaGetSymbolAddress((void**)&p_itch, g_itch);
    cudaGetSymbolAddress((void**)&p_weffT, g_weffT);
    cudaGetSymbolAddress((void**)&p_oh, g_oh);
    cudaGetSymbolAddress((void**)&p_ps, g_ps);

    dim3 t(256);

    // Weff (used in all 3 iterations)
    build_weff_k<<<256, t>>>(recW);

    // input projection
    gemm64<<<dim3(16,8,1), t>>>(x1,  ipW1, p_ps, 1024, 128, 2048, 0);
    combine_k<<<512, t>>>(p_ps, 8, BB*2048, 2048, ipb1, nullptr, p_h1, M_RELU);
    gemm64<<<dim3(16,8,1), t>>>(p_h1, ipW2, p_ps, 2048, 256, 2048, 0);
    combine_k<<<512, t>>>(p_ps, 8, BB*2048, 2048, ipb2, nullptr, p_h, M_NONE);

    // granule: pre + gate mask
    gemm64<<<dim3(64,4,1), t>>>(p_h, encW, p_ps, 2048, 512, 8192, 0);
    combine_k<<<2048, t>>>(p_ps, 4, BB*8192, 8192, encb, nullptr, p_pre, M_NONE);
    gemm64<<<dim3(64,4,1), t>>>(p_pre, gateW, p_ps, 8192, 2048, 8192, 0);
    combine_k<<<2048, t>>>(p_ps, 4, BB*8192, 8192, gateb, nullptr, p_mask, M_MASK);

    // inhibition + sparse + LN
    mask_stats_k<<<64, t>>>();
    sparse_ln_k<<<64, t>>>(ln_g, ln_b);

    // mossy fiber + dropout
    gemm64<<<dim3(4,32,1), t>>>(p_sparse, mfW, p_ps, 8192, 256, 512, 0);
    combine_k<<<128, t>>>(p_ps, 32, BB*512, 512, mfb, mf_cs, p_state, M_MF);

    // CA3 recurrence, 3 iterations
    for (int it=0; it<3; it++) {
        gemm64<<<dim3(4,8,3), t>>>(p_state, sepW, p_ps, 512, 64, 512, CCC*CCC);
        combine3_k<<<128, t>>>(p_ps, 8, sepb, p_sep, 0);
        gemm64<<<dim3(4,8,3), t>>>(p_sep, compW, p_ps, 512, 64, 512, CCC*CCC);
        combine3_k<<<128, t>>>(p_ps, 8, compb, p_comp, 1);
        gemm64<<<dim3(4,16,1), t>>>(p_comp, p_weffT, p_ps, 512, 32, 512, 0);
        combine_k<<<128, t>>>(p_ps, 16, BB*512, 512, nullptr, recb, p_rec, M_RECB);
        gemm64<<<dim3(2,8,1), t>>>(p_rec, itcW1, p_ps, 512, 64, 256, 0);
        combine_k<<<64, t>>>(p_ps, 8, BB*256, 256, itcb1, nullptr, p_itch, M_RELU);
        itc2_k<<<64, t>>>(itcW2, itcb2);
        update_k<<<128, t>>>();
    }

    // output projection
    gemm64<<<dim3(16,4,1), t>>>(p_state, opW1, p_ps, 512, 128, 2048, 0);
    combine_k<<<512, t>>>(p_ps, 4, BB*2048, 2048, opb1, nullptr, p_oh, M_RELU);
    gemm64<<<dim3(8,16,1), t>>>(p_oh, opW2, p_ps, 2048, 128, 1024, 0);
    combine_k<<<256, t>>>(p_ps, 16, BB*1024, 1024, opb2, nullptr, (float*)d_out, M_NONE);
}

// round 7
// speedup vs baseline: 1.2740x; 1.0155x over previous
#include <cuda_runtime.h>
#include <math.h>

#define BB  64
#define HH  2048
#define GG  8192
#define CCC 512
#define RRR 100

// ---- device scratch (no allocations allowed) ----
__device__ float g_h1[BB*HH];
__device__ float g_h [BB*HH];
__device__ float g_pre[BB*GG];
__device__ float g_mask[BB*GG];
__device__ float g_S[BB];
__device__ float g_sparse[BB*GG];
__device__ float g_state[BB*CCC];
__device__ float g_sep[BB*CCC];
__device__ float g_comp[BB*CCC];
__device__ float g_rec[BB*CCC];
__device__ float g_itch[BB*256];
__device__ float g_ic[BB];
__device__ float g_weffT[CCC*CCC];
__device__ float g_oh[BB*HH];
__device__ float g_ps[1<<23];   // split-K partials (32 MB)

// ---- threefry2x32, JAX partitionable: counter (0, idx), out = x0^x1 ----
__device__ __forceinline__ unsigned tf_rotl(unsigned x, int d){ return (x<<d)|(x>>(32-d)); }
__device__ __forceinline__ bool tf_keep(int idx){
    const unsigned ks0=0u, ks1=42u, ks2=0x1BD11BDAu^0u^42u;
    unsigned x0 = 0u + ks0;
    unsigned x1 = (unsigned)idx + ks1;
#define TFR(r) { x0+=x1; x1=tf_rotl(x1,(r)); x1^=x0; }
    TFR(13) TFR(15) TFR(26) TFR(6)  x0+=ks1; x1+=ks2+1u;
    TFR(17) TFR(29) TFR(16) TFR(24) x0+=ks2; x1+=ks0+2u;
    TFR(13) TFR(15) TFR(26) TFR(6)  x0+=ks0; x1+=ks1+3u;
    TFR(17) TFR(29) TFR(16) TFR(24) x0+=ks1; x1+=ks2+4u;
    TFR(13) TFR(15) TFR(26) TFR(6)  x0+=ks2; x1+=ks0+5u;
#undef TFR
    unsigned bits = x0 ^ x1;
    float u = __uint_as_float((bits>>9)|0x3f800000u) - 1.0f;
    return u > 0.1f;
}

// packed f32x2 FMA: acc = a*b + acc
#define FMA2(accv, av, bv) \
    asm("fma.rn.f32x2 %0, %1, %2, %0;" : "+l"(accv) : "l"(av), "l"(bv))
#define DUP2(dst, w) \
    asm("mov.b64 %0, {%1, %1};" : "=l"(dst) : "f"(w))

// ---- split-K GEMM: partial[b,n] = sum_{k in seg} X[b,k]*W[n,k] ----
// 64x128 tile, 256 threads, 8x4 micro-tile in f32x2 row-pairs.
// Chunk K=16, k-major smem, register-prefetch double buffering.
__global__ __launch_bounds__(256,3) void gemm64(
    const float* __restrict__ Xg, const float* __restrict__ Wg,
    float* __restrict__ ps, int K, int Kc, int N, int wzStride)
{
    __shared__ float Xs[16][72];
    __shared__ float Ws[16][136];
    const int tid = threadIdx.x;
    const int n0  = blockIdx.x * 128;
    const int kb  = blockIdx.y * Kc;
    const float* W = Wg + (size_t)blockIdx.z*(size_t)wzStride;
    float* outp = ps + (size_t)(blockIdx.z*gridDim.y + blockIdx.y)*(size_t)(BB*N);

    const int ty = tid >> 5;        // 8 row-groups of 8 rows
    const int tx = tid & 31;        // 32 col-groups of 4 cols

    // staging maps
    const int xr = tid & 63,  xkg = tid >> 6;   // X: row, k-quad (4 k each)
    const int wc = tid & 127, wkg = tid >> 7;   // W: col, k-oct (8 k each)

    unsigned long long acc[4][4];
#pragma unroll
    for (int p=0;p<4;p++)
#pragma unroll
        for (int j=0;j<4;j++) acc[p][j]=0ull;

    // prefetch first chunk
    float4 xa  = *(const float4*)(Xg + (size_t)xr*K + kb + xkg*4);
    float4 wa0 = *(const float4*)(W + (size_t)(n0+wc)*K + kb + wkg*8);
    float4 wa1 = *(const float4*)(W + (size_t)(n0+wc)*K + kb + wkg*8 + 4);

    for (int k0 = kb; k0 < kb + Kc; k0 += 16) {
        Xs[xkg*4+0][xr]=xa.x; Xs[xkg*4+1][xr]=xa.y; Xs[xkg*4+2][xr]=xa.z; Xs[xkg*4+3][xr]=xa.w;
        Ws[wkg*8+0][wc]=wa0.x; Ws[wkg*8+1][wc]=wa0.y; Ws[wkg*8+2][wc]=wa0.z; Ws[wkg*8+3][wc]=wa0.w;
        Ws[wkg*8+4][wc]=wa1.x; Ws[wkg*8+5][wc]=wa1.y; Ws[wkg*8+6][wc]=wa1.z; Ws[wkg*8+7][wc]=wa1.w;
        __syncthreads();

        int kn = k0 + 16;
        if (kn < kb + Kc) {
            xa  = *(const float4*)(Xg + (size_t)xr*K + kn + xkg*4);
            wa0 = *(const float4*)(W + (size_t)(n0+wc)*K + kn + wkg*8);
            wa1 = *(const float4*)(W + (size_t)(n0+wc)*K + kn + wkg*8 + 4);
        }

#pragma unroll
        for (int kk=0; kk<16; ++kk) {
            ulonglong2 a01 = *(const ulonglong2*)&Xs[kk][ty*8];     // rows 0..3 (2 f32x2)
            ulonglong2 a23 = *(const ulonglong2*)&Xs[kk][ty*8+4];   // rows 4..7
            float4 wv = *(const float4*)&Ws[kk][tx*4];
            unsigned long long b0,b1,b2,b3;
            DUP2(b0,wv.x); DUP2(b1,wv.y); DUP2(b2,wv.z); DUP2(b3,wv.w);
            FMA2(acc[0][0],a01.x,b0); FMA2(acc[0][1],a01.x,b1); FMA2(acc[0][2],a01.x,b2); FMA2(acc[0][3],a01.x,b3);
            FMA2(acc[1][0],a01.y,b0); FMA2(acc[1][1],a01.y,b1); FMA2(acc[1][2],a01.y,b2); FMA2(acc[1][3],a01.y,b3);
            FMA2(acc[2][0],a23.x,b0); FMA2(acc[2][1],a23.x,b1); FMA2(acc[2][2],a23.x,b2); FMA2(acc[2][3],a23.x,b3);
            FMA2(acc[3][0],a23.y,b0); FMA2(acc[3][1],a23.y,b1); FMA2(acc[3][2],a23.y,b2); FMA2(acc[3][3],a23.y,b3);
        }
        __syncthreads();
    }

    // epilogue: unpack row-pairs, vectorized float4 stores
#pragma unroll
    for (int p=0;p<4;p++){
        float lo[4], hi[4];
#pragma unroll
        for (int j=0;j<4;j++)
            asm("mov.b64 {%0, %1}, %2;" : "=f"(lo[j]), "=f"(hi[j]) : "l"(acc[p][j]));
        int r0 = ty*8 + 2*p;
        *(float4*)(outp + (size_t)r0    *N + n0 + tx*4) = make_float4(lo[0],lo[1],lo[2],lo[3]);
        *(float4*)(outp + (size_t)(r0+1)*N + n0 + tx*4) = make_float4(hi[0],hi[1],hi[2],hi[3]);
    }
}

// ---- split-K reduce + epilogue ----
#define M_NONE 0
#define M_RELU 1
#define M_MASK 2
#define M_MF   3
#define M_RECB 4
__global__ void combine_k(const float* __restrict__ ps, int KS, int BN, int N,
                          const float* __restrict__ bias, const float* __restrict__ extra,
                          float* __restrict__ out, int mode)
{
    int idx = blockIdx.x*256 + threadIdx.x;
    if (idx >= BN) return;
    float z = 0.0f;
    for (int s=0;s<KS;s++) z += ps[(size_t)s*BN + idx];
    int n = idx % N;
    float v;
    if (mode == M_RECB) { z += extra[idx]; v = fmaxf(z,0.0f); }
    else {
        if (bias) z += bias[n];
        if (mode==M_NONE)      v = z;
        else if (mode==M_RELU) v = fmaxf(z,0.0f);
        else if (mode==M_MASK) { float g = 1.0f/(1.0f+expf(-z)); v = (g>0.1f)?1.0f:0.0f; }
        else { float p = z*extra[n]; v = tf_keep(idx)?p:0.0f; }   // M_MF
    }
    out[idx] = v;
}

// 3-branch running pairwise average: sig=0 -> tanh*0.8, sig=1 -> sigmoid*0.6
__global__ void combine3_k(const float* __restrict__ ps, int KS,
                           const float* __restrict__ bias, float* __restrict__ out, int sig)
{
    int idx = blockIdx.x*256 + threadIdx.x;
    if (idx >= BB*CCC) return;
    int n = idx & (CCC-1);
    float z[3];
#pragma unroll
    for (int br=0;br<3;br++){
        float a = 0.0f;
        for (int s=0;s<KS;s++) a += ps[(size_t)(br*KS+s)*(BB*CCC) + idx];
        z[br] = a + bias[br*CCC + n];
    }
    float v;
    if (!sig){
        v = tanhf(z[0])*0.8f;
        v = (v + tanhf(z[1])*0.8f)*0.5f;
        v = (v + tanhf(z[2])*0.8f)*0.5f;
    } else {
        v = 0.6f/(1.0f+expf(-z[0]));
        v = (v + 0.6f/(1.0f+expf(-z[1])))*0.5f;
        v = (v + 0.6f/(1.0f+expf(-z[2])))*0.5f;
    }
    out[idx] = v;
}

__global__ void mask_stats_k()
{
    __shared__ float red[256];
    int b = blockIdx.x, tid = threadIdx.x;
    float s = 0.0f;
    for (int j=tid;j<GG;j+=256) s += g_mask[(size_t)b*GG + j];
    red[tid]=s; __syncthreads();
    for (int off=128;off;off>>=1){ if(tid<off) red[tid]+=red[tid+off]; __syncthreads(); }
    if (tid==0) g_S[b]=red[0];
}

// inhibition + sparse + LayerNorm; one block per batch row
__global__ void sparse_ln_k(const float* __restrict__ lng, const float* __restrict__ lnb)
{
    __shared__ float sv[GG];
    __shared__ float red[256];
    int b = blockIdx.x, tid = threadIdx.x;
    float tot = 0.0f;
    for (int i=0;i<BB;i++) tot += g_S[i];
    bool anyb = tot > 0.0f;
    float Sb = g_S[b];

    float lsum = 0.0f;
    for (int j=tid;j<GG;j+=256){
        float m = g_mask[(size_t)b*GG + j];
        float p = g_pre [(size_t)b*GG + j];
        if (anyb) p -= 0.1f*(Sb - m);
        float s = p*m;
        sv[j]=s; lsum+=s;
    }
    red[tid]=lsum; __syncthreads();
    for (int off=128;off;off>>=1){ if(tid<off) red[tid]+=red[tid+off]; __syncthreads(); }
    float mu = red[0]/(float)GG; __syncthreads();

    float lsq = 0.0f;
    for (int j=tid;j<GG;j+=256){ float d=sv[j]-mu; lsq+=d*d; }
    red[tid]=lsq; __syncthreads();
    for (int off=128;off;off>>=1){ if(tid<off) red[tid]+=red[tid+off]; __syncthreads(); }
    float rstd = 1.0f/sqrtf(red[0]/(float)GG + 1e-5f);

    for (int j=tid;j<GG;j+=256)
        g_sparse[(size_t)b*GG + j] = (sv[j]-mu)*rstd*lng[j] + lnb[j];
}

// WeffT[h,d] = sum_c strength_c * recW[c,d,h]   (float4-vectorized)
__global__ void build_weff_k(const float* __restrict__ recW)
{
    int g4 = blockIdx.x*256 + threadIdx.x;
    if (g4 >= (CCC*CCC)/4) return;
    float4 acc = make_float4(0.f,0.f,0.f,0.f);
    for (int c=0;c<RRR;c++){
        float s = 1.0f/(1.0f+0.1f*(float)c);
        float4 v = *(const float4*)(recW + (size_t)c*CCC*CCC + g4*4);
        acc.x += s*v.x; acc.y += s*v.y; acc.z += s*v.z; acc.w += s*v.w;
    }
    int gid = g4*4;
#pragma unroll
    for (int j=0;j<4;j++){
        int d = (gid+j) >> 9, h = (gid+j) & (CCC-1);
        g_weffT[(size_t)h*CCC + d] = (&acc.x)[j];
    }
}

__global__ void itc2_k(const float* __restrict__ w2, const float* __restrict__ b2)
{
    __shared__ float red[256];
    int b = blockIdx.x, tid = threadIdx.x;
    red[tid] = g_itch[b*256+tid]*w2[tid]; __syncthreads();
    for (int off=128;off;off>>=1){ if(tid<off) red[tid]+=red[tid+off]; __syncthreads(); }
    if (tid==0) g_ic[b] = 1.0f/(1.0f+expf(-(red[0]+b2[0])));
}

__global__ void update_k()
{
    int idx = blockIdx.x*256 + threadIdx.x;
    if (idx >= BB*CCC) return;
    float ic = g_ic[idx>>9];
    g_state[idx] = (1.0f-ic)*g_state[idx] + ic*g_rec[idx];
}

extern "C" void kernel_launch(void* const* d_in, const int* in_sizes, int n_in,
                              void* d_out, int out_size)
{
    const float* x1    = (const float*)d_in[0];
    const float* ipW1  = (const float*)d_in[1];
    const float* ipb1  = (const float*)d_in[2];
    const float* ipW2  = (const float*)d_in[3];
    const float* ipb2  = (const float*)d_in[4];
    const float* encW  = (const float*)d_in[5];
    const float* encb  = (const float*)d_in[6];
    const float* gateW = (const float*)d_in[7];
    const float* gateb = (const float*)d_in[8];
    const float* ln_g  = (const float*)d_in[9];
    const float* ln_b  = (const float*)d_in[10];
    /* d_in[11] lateral: ones-eye, handled analytically */
    const float* mfW   = (const float*)d_in[12];
    const float* mfb   = (const float*)d_in[13];
    const float* mf_cs = (const float*)d_in[14];
    const float* recW  = (const float*)d_in[15];
    const float* recb  = (const float*)d_in[16];
    const float* sepW  = (const float*)d_in[17];
    const float* sepb  = (const float*)d_in[18];
    const float* compW = (const float*)d_in[19];
    const float* compb = (const float*)d_in[20];
    const float* itcW1 = (const float*)d_in[21];
    const float* itcb1 = (const float*)d_in[22];
    const float* itcW2 = (const float*)d_in[23];
    const float* itcb2 = (const float*)d_in[24];
    const float* opW1  = (const float*)d_in[25];
    const float* opb1  = (const float*)d_in[26];
    const float* opW2  = (const float*)d_in[27];
    const float* opb2  = (const float*)d_in[28];

    float *p_h1,*p_h,*p_pre,*p_mask,*p_sparse,*p_state,*p_sep,*p_comp,*p_rec,*p_itch,*p_weffT,*p_oh,*p_ps;
    cudaGetSymbolAddress((void**)&p_h1, g_h1);
    cudaGetSymbolAddress((void**)&p_h,  g_h);
    cudaGetSymbolAddress((void**)&p_pre, g_pre);
    cudaGetSymbolAddress((void**)&p_mask, g_mask);
    cudaGetSymbolAddress((void**)&p_sparse, g_sparse);
    cudaGetSymbolAddress((void**)&p_state, g_state);
    cudaGetSymbolAddress((void**)&p_sep, g_sep);
    cudaGetSymbolAddress((void**)&p_comp, g_comp);
    cudaGetSymbolAddress((void**)&p_rec, g_rec);
    cudaGetSymbolAddress((void**)&p_itch, g_itch);
    cudaGetSymbolAddress((void**)&p_weffT, g_weffT);
    cudaGetSymbolAddress((void**)&p_oh, g_oh);
    cudaGetSymbolAddress((void**)&p_ps, g_ps);

    dim3 t(256);

    // Weff (used in all 3 iterations)
    build_weff_k<<<256, t>>>(recW);

    // input projection  (grids sized for >=256 CTAs per GEMM)
    gemm64<<<dim3(16,16,1), t>>>(x1,  ipW1, p_ps, 1024, 64, 2048, 0);
    combine_k<<<512, t>>>(p_ps, 16, BB*2048, 2048, ipb1, nullptr, p_h1, M_RELU);
    gemm64<<<dim3(16,32,1), t>>>(p_h1, ipW2, p_ps, 2048, 64, 2048, 0);
    combine_k<<<512, t>>>(p_ps, 32, BB*2048, 2048, ipb2, nullptr, p_h, M_NONE);

    // granule: pre + gate mask
    gemm64<<<dim3(64,8,1), t>>>(p_h, encW, p_ps, 2048, 256, 8192, 0);
    combine_k<<<2048, t>>>(p_ps, 8, BB*8192, 8192, encb, nullptr, p_pre, M_NONE);
    gemm64<<<dim3(64,8,1), t>>>(p_pre, gateW, p_ps, 8192, 1024, 8192, 0);
    combine_k<<<2048, t>>>(p_ps, 8, BB*8192, 8192, gateb, nullptr, p_mask, M_MASK);

    // inhibition + sparse + LN
    mask_stats_k<<<64, t>>>();
    sparse_ln_k<<<64, t>>>(ln_g, ln_b);

    // mossy fiber + dropout
    gemm64<<<dim3(4,64,1), t>>>(p_sparse, mfW, p_ps, 8192, 128, 512, 0);
    combine_k<<<128, t>>>(p_ps, 64, BB*512, 512, mfb, mf_cs, p_state, M_MF);

    // CA3 recurrence, 3 iterations
    for (int it=0; it<3; it++) {
        gemm64<<<dim3(4,16,3), t>>>(p_state, sepW, p_ps, 512, 32, 512, CCC*CCC);
        combine3_k<<<128, t>>>(p_ps, 16, sepb, p_sep, 0);
        gemm64<<<dim3(4,16,3), t>>>(p_sep, compW, p_ps, 512, 32, 512, CCC*CCC);
        combine3_k<<<128, t>>>(p_ps, 16, compb, p_comp, 1);
        gemm64<<<dim3(4,16,1), t>>>(p_comp, p_weffT, p_ps, 512, 32, 512, 0);
        combine_k<<<128, t>>>(p_ps, 16, BB*512, 512, nullptr, recb, p_rec, M_RECB);
        gemm64<<<dim3(2,16,1), t>>>(p_rec, itcW1, p_ps, 512, 32, 256, 0);
        combine_k<<<64, t>>>(p_ps, 16, BB*256, 256, itcb1, nullptr, p_itch, M_RELU);
        itc2_k<<<64, t>>>(itcW2, itcb2);
        update_k<<<128, t>>>();
    }

    // output projection
    gemm64<<<dim3(16,16,1), t>>>(p_state, opW1, p_ps, 512, 32, 2048, 0);
    combine_k<<<512, t>>>(p_ps, 16, BB*2048, 2048, opb1, nullptr, p_oh, M_RELU);
    gemm64<<<dim3(8,32,1), t>>>(p_oh, opW2, p_ps, 2048, 64, 1024, 0);
    combine_k<<<256, t>>>(p_ps, 32, BB*1024, 1024, opb2, nullptr, (float*)d_out, M_NONE);
}

// round 8
// speedup vs baseline: 1.2953x; 1.0168x over previous
#include <cuda_runtime.h>
#include <math.h>

#define BB  64
#define HH  2048
#define GG  8192
#define CCC 512
#define RRR 100

// ---- device scratch (no allocations allowed) ----
__device__ float g_h1[BB*HH];
__device__ float g_h [BB*HH];
__device__ float g_pre[BB*GG];
__device__ float g_mask[BB*GG];
__device__ float g_S[BB];
__device__ float g_sparse[BB*GG];
__device__ float g_state[BB*CCC];
__device__ float g_sep[BB*CCC];
__device__ float g_comp[BB*CCC];
__device__ float g_rec[BB*CCC];
__device__ float g_itch[BB*256];
__device__ float g_ic[BB];
__device__ float g_weffT[CCC*CCC];
__device__ float g_oh[BB*HH];
__device__ float g_ps[1<<24];   // split-K partials (64 MB)

// ---- threefry2x32, JAX partitionable: counter (0, idx), out = x0^x1 ----
__device__ __forceinline__ unsigned tf_rotl(unsigned x, int d){ return (x<<d)|(x>>(32-d)); }
__device__ __forceinline__ bool tf_keep(int idx){
    const unsigned ks0=0u, ks1=42u, ks2=0x1BD11BDAu^0u^42u;
    unsigned x0 = 0u + ks0;
    unsigned x1 = (unsigned)idx + ks1;
#define TFR(r) { x0+=x1; x1=tf_rotl(x1,(r)); x1^=x0; }
    TFR(13) TFR(15) TFR(26) TFR(6)  x0+=ks1; x1+=ks2+1u;
    TFR(17) TFR(29) TFR(16) TFR(24) x0+=ks2; x1+=ks0+2u;
    TFR(13) TFR(15) TFR(26) TFR(6)  x0+=ks0; x1+=ks1+3u;
    TFR(17) TFR(29) TFR(16) TFR(24) x0+=ks1; x1+=ks2+4u;
    TFR(13) TFR(15) TFR(26) TFR(6)  x0+=ks2; x1+=ks0+5u;
#undef TFR
    unsigned bits = x0 ^ x1;
    float u = __uint_as_float((bits>>9)|0x3f800000u) - 1.0f;
    return u > 0.1f;
}

// packed f32x2 FMA: acc = a*b + acc
#define FMA2(accv, av, bv) \
    asm("fma.rn.f32x2 %0, %1, %2, %0;" : "+l"(accv) : "l"(av), "l"(bv))
#define DUP2(dst, w) \
    asm("mov.b64 %0, {%1, %1};" : "=l"(dst) : "f"(w))

// ---- split-K GEMM: partial[b,n] = sum_{k in seg} X[b,k]*W[n,k] ----
// 64x256 tile, 256 threads, 16x4 micro-tile (broadcast-heavy a-operand).
// Chunk K=16, k-major smem, register-prefetch double buffering.
__global__ __launch_bounds__(256,2) void gemm64(
    const float* __restrict__ Xg, const float* __restrict__ Wg,
    float* __restrict__ ps, int K, int Kc, int N, int wzStride)
{
    __shared__ float Xs[16][72];    // stride 288B (16B-aligned)
    __shared__ float Ws[16][260];   // stride 1040B (16B-aligned)
    const int tid = threadIdx.x;
    const int n0  = blockIdx.x * 256;
    const int kb  = blockIdx.y * Kc;
    const float* W = Wg + (size_t)blockIdx.z*(size_t)wzStride;
    float* outp = ps + (size_t)(blockIdx.z*gridDim.y + blockIdx.y)*(size_t)(BB*N);

    const int ty = tid >> 6;        // 4 row-groups of 16 rows
    const int tx = tid & 63;        // 64 col-groups of 4 cols

    // staging maps
    const int xr = tid & 63, xkg = tid >> 6;  // X: row, k-quad
    const int wc = tid;                        // W: one col per thread, all 16 k

    unsigned long long acc[8][4];
#pragma unroll
    for (int p=0;p<8;p++)
#pragma unroll
        for (int j=0;j<4;j++) acc[p][j]=0ull;

    // prefetch first chunk
    float4 xa = *(const float4*)(Xg + (size_t)xr*K + kb + xkg*4);
    float4 wa0 = *(const float4*)(W + (size_t)(n0+wc)*K + kb);
    float4 wa1 = *(const float4*)(W + (size_t)(n0+wc)*K + kb + 4);
    float4 wa2 = *(const float4*)(W + (size_t)(n0+wc)*K + kb + 8);
    float4 wa3 = *(const float4*)(W + (size_t)(n0+wc)*K + kb + 12);

    for (int k0 = kb; k0 < kb + Kc; k0 += 16) {
        Xs[xkg*4+0][xr]=xa.x; Xs[xkg*4+1][xr]=xa.y; Xs[xkg*4+2][xr]=xa.z; Xs[xkg*4+3][xr]=xa.w;
        Ws[ 0][wc]=wa0.x; Ws[ 1][wc]=wa0.y; Ws[ 2][wc]=wa0.z; Ws[ 3][wc]=wa0.w;
        Ws[ 4][wc]=wa1.x; Ws[ 5][wc]=wa1.y; Ws[ 6][wc]=wa1.z; Ws[ 7][wc]=wa1.w;
        Ws[ 8][wc]=wa2.x; Ws[ 9][wc]=wa2.y; Ws[10][wc]=wa2.z; Ws[11][wc]=wa2.w;
        Ws[12][wc]=wa3.x; Ws[13][wc]=wa3.y; Ws[14][wc]=wa3.z; Ws[15][wc]=wa3.w;
        __syncthreads();

        int kn = k0 + 16;
        if (kn < kb + Kc) {
            xa  = *(const float4*)(Xg + (size_t)xr*K + kn + xkg*4);
            wa0 = *(const float4*)(W + (size_t)(n0+wc)*K + kn);
            wa1 = *(const float4*)(W + (size_t)(n0+wc)*K + kn + 4);
            wa2 = *(const float4*)(W + (size_t)(n0+wc)*K + kn + 8);
            wa3 = *(const float4*)(W + (size_t)(n0+wc)*K + kn + 12);
        }

#pragma unroll
        for (int kk=0; kk<16; ++kk) {
            // a: 16 rows = 8 f32x2, broadcast within warp (4 LDS.128, 1 wf each)
            ulonglong2 aA = *(const ulonglong2*)&Xs[kk][ty*16];
            ulonglong2 aB = *(const ulonglong2*)&Xs[kk][ty*16+4];
            ulonglong2 aC = *(const ulonglong2*)&Xs[kk][ty*16+8];
            ulonglong2 aD = *(const ulonglong2*)&Xs[kk][ty*16+12];
            // w: 4 cols per lane (1 LDS.128)
            float4 wv = *(const float4*)&Ws[kk][tx*4];
            unsigned long long b0,b1,b2,b3;
            DUP2(b0,wv.x); DUP2(b1,wv.y); DUP2(b2,wv.z); DUP2(b3,wv.w);
            FMA2(acc[0][0],aA.x,b0); FMA2(acc[0][1],aA.x,b1); FMA2(acc[0][2],aA.x,b2); FMA2(acc[0][3],aA.x,b3);
            FMA2(acc[1][0],aA.y,b0); FMA2(acc[1][1],aA.y,b1); FMA2(acc[1][2],aA.y,b2); FMA2(acc[1][3],aA.y,b3);
            FMA2(acc[2][0],aB.x,b0); FMA2(acc[2][1],aB.x,b1); FMA2(acc[2][2],aB.x,b2); FMA2(acc[2][3],aB.x,b3);
            FMA2(acc[3][0],aB.y,b0); FMA2(acc[3][1],aB.y,b1); FMA2(acc[3][2],aB.y,b2); FMA2(acc[3][3],aB.y,b3);
            FMA2(acc[4][0],aC.x,b0); FMA2(acc[4][1],aC.x,b1); FMA2(acc[4][2],aC.x,b2); FMA2(acc[4][3],aC.x,b3);
            FMA2(acc[5][0],aC.y,b0); FMA2(acc[5][1],aC.y,b1); FMA2(acc[5][2],aC.y,b2); FMA2(acc[5][3],aC.y,b3);
            FMA2(acc[6][0],aD.x,b0); FMA2(acc[6][1],aD.x,b1); FMA2(acc[6][2],aD.x,b2); FMA2(acc[6][3],aD.x,b3);
            FMA2(acc[7][0],aD.y,b0); FMA2(acc[7][1],aD.y,b1); FMA2(acc[7][2],aD.y,b2); FMA2(acc[7][3],aD.y,b3);
        }
        __syncthreads();
    }

    // epilogue: unpack row-pairs, vectorized float4 stores
#pragma unroll
    for (int p=0;p<8;p++){
        float lo[4], hi[4];
#pragma unroll
        for (int j=0;j<4;j++)
            asm("mov.b64 {%0, %1}, %2;" : "=f"(lo[j]), "=f"(hi[j]) : "l"(acc[p][j]));
        int r0 = ty*16 + 2*p;
        *(float4*)(outp + (size_t)r0    *N + n0 + tx*4) = make_float4(lo[0],lo[1],lo[2],lo[3]);
        *(float4*)(outp + (size_t)(r0+1)*N + n0 + tx*4) = make_float4(hi[0],hi[1],hi[2],hi[3]);
    }
}

// ---- split-K reduce + epilogue ----
#define M_NONE 0
#define M_RELU 1
#define M_MASK 2
#define M_MF   3
#define M_RECB 4
__global__ void combine_k(const float* __restrict__ ps, int KS, int BN, int N,
                          const float* __restrict__ bias, const float* __restrict__ extra,
                          float* __restrict__ out, int mode)
{
    int idx = blockIdx.x*256 + threadIdx.x;
    if (idx >= BN) return;
    float z = 0.0f;
    for (int s=0;s<KS;s++) z += ps[(size_t)s*BN + idx];
    int n = idx % N;
    float v;
    if (mode == M_RECB) { z += extra[idx]; v = fmaxf(z,0.0f); }
    else {
        if (bias) z += bias[n];
        if (mode==M_NONE)      v = z;
        else if (mode==M_RELU) v = fmaxf(z,0.0f);
        else if (mode==M_MASK) { float g = 1.0f/(1.0f+expf(-z)); v = (g>0.1f)?1.0f:0.0f; }
        else { float p = z*extra[n]; v = tf_keep(idx)?p:0.0f; }   // M_MF
    }
    out[idx] = v;
}

// 3-branch running pairwise average: sig=0 -> tanh*0.8, sig=1 -> sigmoid*0.6
__global__ void combine3_k(const float* __restrict__ ps, int KS,
                           const float* __restrict__ bias, float* __restrict__ out, int sig)
{
    int idx = blockIdx.x*256 + threadIdx.x;
    if (idx >= BB*CCC) return;
    int n = idx & (CCC-1);
    float z[3];
#pragma unroll
    for (int br=0;br<3;br++){
        float a = 0.0f;
        for (int s=0;s<KS;s++) a += ps[(size_t)(br*KS+s)*(BB*CCC) + idx];
        z[br] = a + bias[br*CCC + n];
    }
    float v;
    if (!sig){
        v = tanhf(z[0])*0.8f;
        v = (v + tanhf(z[1])*0.8f)*0.5f;
        v = (v + tanhf(z[2])*0.8f)*0.5f;
    } else {
        v = 0.6f/(1.0f+expf(-z[0]));
        v = (v + 0.6f/(1.0f+expf(-z[1])))*0.5f;
        v = (v + 0.6f/(1.0f+expf(-z[2])))*0.5f;
    }
    out[idx] = v;
}

__global__ void mask_stats_k()
{
    __shared__ float red[256];
    int b = blockIdx.x, tid = threadIdx.x;
    float s = 0.0f;
    for (int j=tid;j<GG;j+=256) s += g_mask[(size_t)b*GG + j];
    red[tid]=s; __syncthreads();
    for (int off=128;off;off>>=1){ if(tid<off) red[tid]+=red[tid+off]; __syncthreads(); }
    if (tid==0) g_S[b]=red[0];
}

// inhibition + sparse + LayerNorm; one block per batch row
__global__ void sparse_ln_k(const float* __restrict__ lng, const float* __restrict__ lnb)
{
    __shared__ float sv[GG];
    __shared__ float red[256];
    int b = blockIdx.x, tid = threadIdx.x;
    float tot = 0.0f;
    for (int i=0;i<BB;i++) tot += g_S[i];
    bool anyb = tot > 0.0f;
    float Sb = g_S[b];

    float lsum = 0.0f;
    for (int j=tid;j<GG;j+=256){
        float m = g_mask[(size_t)b*GG + j];
        float p = g_pre [(size_t)b*GG + j];
        if (anyb) p -= 0.1f*(Sb - m);
        float s = p*m;
        sv[j]=s; lsum+=s;
    }
    red[tid]=lsum; __syncthreads();
    for (int off=128;off;off>>=1){ if(tid<off) red[tid]+=red[tid+off]; __syncthreads(); }
    float mu = red[0]/(float)GG; __syncthreads();

    float lsq = 0.0f;
    for (int j=tid;j<GG;j+=256){ float d=sv[j]-mu; lsq+=d*d; }
    red[tid]=lsq; __syncthreads();
    for (int off=128;off;off>>=1){ if(tid<off) red[tid]+=red[tid+off]; __syncthreads(); }
    float rstd = 1.0f/sqrtf(red[0]/(float)GG + 1e-5f);

    for (int j=tid;j<GG;j+=256)
        g_sparse[(size_t)b*GG + j] = (sv[j]-mu)*rstd*lng[j] + lnb[j];
}

// WeffT[h,d] = sum_c strength_c * recW[c,d,h]   (float4-vectorized)
__global__ void build_weff_k(const float* __restrict__ recW)
{
    int g4 = blockIdx.x*256 + threadIdx.x;
    if (g4 >= (CCC*CCC)/4) return;
    float4 acc = make_float4(0.f,0.f,0.f,0.f);
    for (int c=0;c<RRR;c++){
        float s = 1.0f/(1.0f+0.1f*(float)c);
        float4 v = *(const float4*)(recW + (size_t)c*CCC*CCC + g4*4);
        acc.x += s*v.x; acc.y += s*v.y; acc.z += s*v.z; acc.w += s*v.w;
    }
    int gid = g4*4;
#pragma unroll
    for (int j=0;j<4;j++){
        int d = (gid+j) >> 9, h = (gid+j) & (CCC-1);
        g_weffT[(size_t)h*CCC + d] = (&acc.x)[j];
    }
}

__global__ void itc2_k(const float* __restrict__ w2, const float* __restrict__ b2)
{
    __shared__ float red[256];
    int b = blockIdx.x, tid = threadIdx.x;
    red[tid] = g_itch[b*256+tid]*w2[tid]; __syncthreads();
    for (int off=128;off;off>>=1){ if(tid<off) red[tid]+=red[tid+off]; __syncthreads(); }
    if (tid==0) g_ic[b] = 1.0f/(1.0f+expf(-(red[0]+b2[0])));
}

__global__ void update_k()
{
    int idx = blockIdx.x*256 + threadIdx.x;
    if (idx >= BB*CCC) return;
    float ic = g_ic[idx>>9];
    g_state[idx] = (1.0f-ic)*g_state[idx] + ic*g_rec[idx];
}

extern "C" void kernel_launch(void* const* d_in, const int* in_sizes, int n_in,
                              void* d_out, int out_size)
{
    const float* x1    = (const float*)d_in[0];
    const float* ipW1  = (const float*)d_in[1];
    const float* ipb1  = (const float*)d_in[2];
    const float* ipW2  = (const float*)d_in[3];
    const float* ipb2  = (const float*)d_in[4];
    const float* encW  = (const float*)d_in[5];
    const float* encb  = (const float*)d_in[6];
    const float* gateW = (const float*)d_in[7];
    const float* gateb = (const float*)d_in[8];
    const float* ln_g  = (const float*)d_in[9];
    const float* ln_b  = (const float*)d_in[10];
    /* d_in[11] lateral: ones-eye, handled analytically */
    const float* mfW   = (const float*)d_in[12];
    const float* mfb   = (const float*)d_in[13];
    const float* mf_cs = (const float*)d_in[14];
    const float* recW  = (const float*)d_in[15];
    const float* recb  = (const float*)d_in[16];
    const float* sepW  = (const float*)d_in[17];
    const float* sepb  = (const float*)d_in[18];
    const float* compW = (const float*)d_in[19];
    const float* compb = (const float*)d_in[20];
    const float* itcW1 = (const float*)d_in[21];
    const float* itcb1 = (const float*)d_in[22];
    const float* itcW2 = (const float*)d_in[23];
    const float* itcb2 = (const float*)d_in[24];
    const float* opW1  = (const float*)d_in[25];
    const float* opb1  = (const float*)d_in[26];
    const float* opW2  = (const float*)d_in[27];
    const float* opb2  = (const float*)d_in[28];

    float *p_h1,*p_h,*p_pre,*p_mask,*p_sparse,*p_state,*p_sep,*p_comp,*p_rec,*p_itch,*p_weffT,*p_oh,*p_ps;
    cudaGetSymbolAddress((void**)&p_h1, g_h1);
    cudaGetSymbolAddress((void**)&p_h,  g_h);
    cudaGetSymbolAddress((void**)&p_pre, g_pre);
    cudaGetSymbolAddress((void**)&p_mask, g_mask);
    cudaGetSymbolAddress((void**)&p_sparse, g_sparse);
    cudaGetSymbolAddress((void**)&p_state, g_state);
    cudaGetSymbolAddress((void**)&p_sep, g_sep);
    cudaGetSymbolAddress((void**)&p_comp, g_comp);
    cudaGetSymbolAddress((void**)&p_rec, g_rec);
    cudaGetSymbolAddress((void**)&p_itch, g_itch);
    cudaGetSymbolAddress((void**)&p_weffT, g_weffT);
    cudaGetSymbolAddress((void**)&p_oh, g_oh);
    cudaGetSymbolAddress((void**)&p_ps, g_ps);

    dim3 t(256);

    // Weff (used in all 3 iterations)
    build_weff_k<<<256, t>>>(recW);

    // input projection
    gemm64<<<dim3(8,32,1), t>>>(x1,  ipW1, p_ps, 1024, 32, 2048, 0);
    combine_k<<<512, t>>>(p_ps, 32, BB*2048, 2048, ipb1, nullptr, p_h1, M_RELU);
    gemm64<<<dim3(8,32,1), t>>>(p_h1, ipW2, p_ps, 2048, 64, 2048, 0);
    combine_k<<<512, t>>>(p_ps, 32, BB*2048, 2048, ipb2, nullptr, p_h, M_NONE);

    // granule: pre + gate mask
    gemm64<<<dim3(32,8,1), t>>>(p_h, encW, p_ps, 2048, 256, 8192, 0);
    combine_k<<<2048, t>>>(p_ps, 8, BB*8192, 8192, encb, nullptr, p_pre, M_NONE);
    gemm64<<<dim3(32,16,1), t>>>(p_pre, gateW, p_ps, 8192, 512, 8192, 0);
    combine_k<<<2048, t>>>(p_ps, 16, BB*8192, 8192, gateb, nullptr, p_mask, M_MASK);

    // inhibition + sparse + LN
    mask_stats_k<<<64, t>>>();
    sparse_ln_k<<<64, t>>>(ln_g, ln_b);

    // mossy fiber + dropout
    gemm64<<<dim3(2,128,1), t>>>(p_sparse, mfW, p_ps, 8192, 64, 512, 0);
    combine_k<<<128, t>>>(p_ps, 128, BB*512, 512, mfb, mf_cs, p_state, M_MF);

    // CA3 recurrence, 3 iterations
    for (int it=0; it<3; it++) {
        gemm64<<<dim3(2,32,3), t>>>(p_state, sepW, p_ps, 512, 16, 512, CCC*CCC);
        combine3_k<<<128, t>>>(p_ps, 32, sepb, p_sep, 0);
        gemm64<<<dim3(2,32,3), t>>>(p_sep, compW, p_ps, 512, 16, 512, CCC*CCC);
        combine3_k<<<128, t>>>(p_ps, 32, compb, p_comp, 1);
        gemm64<<<dim3(2,32,1), t>>>(p_comp, p_weffT, p_ps, 512, 16, 512, 0);
        combine_k<<<128, t>>>(p_ps, 32, BB*512, 512, nullptr, recb, p_rec, M_RECB);
        gemm64<<<dim3(1,32,1), t>>>(p_rec, itcW1, p_ps, 512, 16, 256, 0);
        combine_k<<<64, t>>>(p_ps, 32, BB*256, 256, itcb1, nullptr, p_itch, M_RELU);
        itc2_k<<<64, t>>>(itcW2, itcb2);
        update_k<<<128, t>>>();
    }

    // output projection
    gemm64<<<dim3(8,32,1), t>>>(p_state, opW1, p_ps, 512, 16, 2048, 0);
    combine_k<<<512, t>>>(p_ps, 32, BB*2048, 2048, opb1, nullptr, p_oh, M_RELU);
    gemm64<<<dim3(4,64,1), t>>>(p_oh, opW2, p_ps, 2048, 32, 1024, 0);
    combine_k<<<256, t>>>(p_ps, 64, BB*1024, 1024, opb2, nullptr, (float*)d_out, M_NONE);
}

// round 11
// speedup vs baseline: 1.3543x; 1.0456x over previous
#include <cuda_runtime.h>
#include <cuda_bf16.h>
#include <cstdint>
#include <math.h>

#define BB  64
#define HH  2048
#define GG  8192
#define CCC 512
#define RRR 100
#define GRID_REC 128

// ---- device scratch ----
__device__ float g_h1[BB*HH];
__device__ float g_h [BB*HH];
__device__ float g_pre[BB*GG];
__device__ float g_mask[BB*GG];
__device__ float g_S[BB];
__device__ float g_sparse[BB*GG];
__device__ float g_state[BB*CCC];
__device__ float g_sep[BB*CCC];
__device__ float g_comp[BB*CCC];
__device__ float g_rec[BB*CCC];
__device__ float g_itch[BB*256];
__device__ float g_ic[BB];
__device__ float g_weffT[CCC*CCC];
__device__ float g_oh[BB*HH];
__device__ float g_ps[1<<24];   // split-K partials
__device__ int   g_bars[64];

// ---- threefry2x32 (JAX partitionable) ----
__device__ __forceinline__ unsigned tf_rotl(unsigned x,int d){ return (x<<d)|(x>>(32-d)); }
__device__ __forceinline__ bool tf_keep(int idx){
    const unsigned ks0=0u, ks1=42u, ks2=0x1BD11BDAu^0u^42u;
    unsigned x0 = 0u + ks0;
    unsigned x1 = (unsigned)idx + ks1;
#define TFR(r) { x0+=x1; x1=tf_rotl(x1,(r)); x1^=x0; }
    TFR(13) TFR(15) TFR(26) TFR(6)  x0+=ks1; x1+=ks2+1u;
    TFR(17) TFR(29) TFR(16) TFR(24) x0+=ks2; x1+=ks0+2u;
    TFR(13) TFR(15) TFR(26) TFR(6)  x0+=ks0; x1+=ks1+3u;
    TFR(17) TFR(29) TFR(16) TFR(24) x0+=ks1; x1+=ks2+4u;
    TFR(13) TFR(15) TFR(26) TFR(6)  x0+=ks2; x1+=ks0+5u;
#undef TFR
    unsigned bits = x0 ^ x1;
    float u = __uint_as_float((bits>>9)|0x3f800000u) - 1.0f;
    return u > 0.1f;
}

// ---- scalar split-K GEMM (R8, proven) ----
#define FMA2(accv, av, bv) asm("fma.rn.f32x2 %0, %1, %2, %0;" : "+l"(accv) : "l"(av), "l"(bv))
#define DUP2(dst, w) asm("mov.b64 %0, {%1, %1};" : "=l"(dst) : "f"(w))
__global__ __launch_bounds__(256,2) void gemm64(
    const float* __restrict__ Xg, const float* __restrict__ Wg,
    float* __restrict__ ps, int K, int Kc, int N, int wzStride)
{
    __shared__ float Xs[16][72];
    __shared__ float Ws[16][260];
    const int tid = threadIdx.x;
    const int n0  = blockIdx.x * 256;
    const int kb  = blockIdx.y * Kc;
    const float* W = Wg + (size_t)blockIdx.z*(size_t)wzStride;
    float* outp = ps + (size_t)(blockIdx.z*gridDim.y + blockIdx.y)*(size_t)(BB*N);
    const int ty = tid >> 6, tx = tid & 63;
    const int xr = tid & 63, xkg = tid >> 6;
    const int wc = tid;

    unsigned long long acc[8][4];
#pragma unroll
    for (int p=0;p<8;p++)
#pragma unroll
        for (int j=0;j<4;j++) acc[p][j]=0ull;

    float4 xa = *(const float4*)(Xg + (size_t)xr*K + kb + xkg*4);
    float4 wa0 = *(const float4*)(W + (size_t)(n0+wc)*K + kb);
    float4 wa1 = *(const float4*)(W + (size_t)(n0+wc)*K + kb + 4);
    float4 wa2 = *(const float4*)(W + (size_t)(n0+wc)*K + kb + 8);
    float4 wa3 = *(const float4*)(W + (size_t)(n0+wc)*K + kb + 12);

    for (int k0 = kb; k0 < kb + Kc; k0 += 16) {
        Xs[xkg*4+0][xr]=xa.x; Xs[xkg*4+1][xr]=xa.y; Xs[xkg*4+2][xr]=xa.z; Xs[xkg*4+3][xr]=xa.w;
        Ws[ 0][wc]=wa0.x; Ws[ 1][wc]=wa0.y; Ws[ 2][wc]=wa0.z; Ws[ 3][wc]=wa0.w;
        Ws[ 4][wc]=wa1.x; Ws[ 5][wc]=wa1.y; Ws[ 6][wc]=wa1.z; Ws[ 7][wc]=wa1.w;
        Ws[ 8][wc]=wa2.x; Ws[ 9][wc]=wa2.y; Ws[10][wc]=wa2.z; Ws[11][wc]=wa2.w;
        Ws[12][wc]=wa3.x; Ws[13][wc]=wa3.y; Ws[14][wc]=wa3.z; Ws[15][wc]=wa3.w;
        __syncthreads();
        int kn = k0 + 16;
        if (kn < kb + Kc) {
            xa  = *(const float4*)(Xg + (size_t)xr*K + kn + xkg*4);
            wa0 = *(const float4*)(W + (size_t)(n0+wc)*K + kn);
            wa1 = *(const float4*)(W + (size_t)(n0+wc)*K + kn + 4);
            wa2 = *(const float4*)(W + (size_t)(n0+wc)*K + kn + 8);
            wa3 = *(const float4*)(W + (size_t)(n0+wc)*K + kn + 12);
        }
#pragma unroll
        for (int kk=0; kk<16; ++kk) {
            ulonglong2 aA = *(const ulonglong2*)&Xs[kk][ty*16];
            ulonglong2 aB = *(const ulonglong2*)&Xs[kk][ty*16+4];
            ulonglong2 aC = *(const ulonglong2*)&Xs[kk][ty*16+8];
            ulonglong2 aD = *(const ulonglong2*)&Xs[kk][ty*16+12];
            float4 wv = *(const float4*)&Ws[kk][tx*4];
            unsigned long long b0,b1,b2,b3;
            DUP2(b0,wv.x); DUP2(b1,wv.y); DUP2(b2,wv.z); DUP2(b3,wv.w);
            FMA2(acc[0][0],aA.x,b0); FMA2(acc[0][1],aA.x,b1); FMA2(acc[0][2],aA.x,b2); FMA2(acc[0][3],aA.x,b3);
            FMA2(acc[1][0],aA.y,b0); FMA2(acc[1][1],aA.y,b1); FMA2(acc[1][2],aA.y,b2); FMA2(acc[1][3],aA.y,b3);
            FMA2(acc[2][0],aB.x,b0); FMA2(acc[2][1],aB.x,b1); FMA2(acc[2][2],aB.x,b2); FMA2(acc[2][3],aB.x,b3);
            FMA2(acc[3][0],aB.y,b0); FMA2(acc[3][1],aB.y,b1); FMA2(acc[3][2],aB.y,b2); FMA2(acc[3][3],aB.y,b3);
            FMA2(acc[4][0],aC.x,b0); FMA2(acc[4][1],aC.x,b1); FMA2(acc[4][2],aC.x,b2); FMA2(acc[4][3],aC.x,b3);
            FMA2(acc[5][0],aC.y,b0); FMA2(acc[5][1],aC.y,b1); FMA2(acc[5][2],aC.y,b2); FMA2(acc[5][3],aC.y,b3);
            FMA2(acc[6][0],aD.x,b0); FMA2(acc[6][1],aD.x,b1); FMA2(acc[6][2],aD.x,b2); FMA2(acc[6][3],aD.x,b3);
            FMA2(acc[7][0],aD.y,b0); FMA2(acc[7][1],aD.y,b1); FMA2(acc[7][2],aD.y,b2); FMA2(acc[7][3],aD.y,b3);
        }
        __syncthreads();
    }
#pragma unroll
    for (int p=0;p<8;p++){
        float lo[4], hi[4];
#pragma unroll
        for (int j=0;j<4;j++)
            asm("mov.b64 {%0, %1}, %2;" : "=f"(lo[j]), "=f"(hi[j]) : "l"(acc[p][j]));
        int r0 = ty*16 + 2*p;
        *(float4*)(outp + (size_t)r0    *N + n0 + tx*4) = make_float4(lo[0],lo[1],lo[2],lo[3]);
        *(float4*)(outp + (size_t)(r0+1)*N + n0 + tx*4) = make_float4(hi[0],hi[1],hi[2],hi[3]);
    }
}

// ---- combines / elementwise ----
#define M_NONE 0
#define M_RELU 1
#define M_MASK 2
#define M_MF   3
__global__ void combine_k(const float* __restrict__ ps, int KS, int BN, int N,
                          const float* __restrict__ bias, const float* __restrict__ extra,
                          float* __restrict__ out, int mode)
{
    int idx = blockIdx.x*256 + threadIdx.x;
    if (idx >= BN) return;
    float z = 0.0f;
    for (int s=0;s<KS;s++) z += ps[(size_t)s*BN + idx];
    int n = idx % N;
    float v;
    if (bias) z += bias[n];
    if (mode==M_NONE)      v = z;
    else if (mode==M_RELU) v = fmaxf(z,0.0f);
    else if (mode==M_MASK) { float g = 1.0f/(1.0f+expf(-z)); v = (g>0.1f)?1.0f:0.0f; }
    else { float p = z*extra[n]; v = tf_keep(idx)?p:0.0f; }
    out[idx] = v;
}
__global__ void mask_stats_k()
{
    __shared__ float red[256];
    int b = blockIdx.x, tid = threadIdx.x;
    float s = 0.0f;
    for (int j=tid;j<GG;j+=256) s += g_mask[(size_t)b*GG + j];
    red[tid]=s; __syncthreads();
    for (int off=128;off;off>>=1){ if(tid<off) red[tid]+=red[tid+off]; __syncthreads(); }
    if (tid==0) g_S[b]=red[0];
}
__global__ void sparse_ln_k(const float* __restrict__ lng, const float* __restrict__ lnb)
{
    __shared__ float sv[GG];
    __shared__ float red[256];
    int b = blockIdx.x, tid = threadIdx.x;
    float tot = 0.0f;
    for (int i=0;i<BB;i++) tot += g_S[i];
    bool anyb = tot > 0.0f;
    float Sb = g_S[b];
    float lsum = 0.0f;
    for (int j=tid;j<GG;j+=256){
        float m = g_mask[(size_t)b*GG + j];
        float p = g_pre [(size_t)b*GG + j];
        if (anyb) p -= 0.1f*(Sb - m);
        float s = p*m;
        sv[j]=s; lsum+=s;
    }
    red[tid]=lsum; __syncthreads();
    for (int off=128;off;off>>=1){ if(tid<off) red[tid]+=red[tid+off]; __syncthreads(); }
    float mu = red[0]/(float)GG; __syncthreads();
    float lsq = 0.0f;
    for (int j=tid;j<GG;j+=256){ float d=sv[j]-mu; lsq+=d*d; }
    red[tid]=lsq; __syncthreads();
    for (int off=128;off;off>>=1){ if(tid<off) red[tid]+=red[tid+off]; __syncthreads(); }
    float rstd = 1.0f/sqrtf(red[0]/(float)GG + 1e-5f);
    for (int j=tid;j<GG;j+=256)
        g_sparse[(size_t)b*GG + j] = (sv[j]-mu)*rstd*lng[j] + lnb[j];
}
__global__ void build_weff_k(const float* __restrict__ recW)
{
    int g4 = blockIdx.x*256 + threadIdx.x;
    if (g4 >= (CCC*CCC)/4) return;
    float4 acc = make_float4(0.f,0.f,0.f,0.f);
    for (int c=0;c<RRR;c++){
        float s = 1.0f/(1.0f+0.1f*(float)c);
        float4 v = *(const float4*)(recW + (size_t)c*CCC*CCC + g4*4);
        acc.x += s*v.x; acc.y += s*v.y; acc.z += s*v.z; acc.w += s*v.w;
    }
    int gid = g4*4;
#pragma unroll
    for (int j=0;j<4;j++){
        int d = (gid+j) >> 9, h = (gid+j) & (CCC-1);
        g_weffT[(size_t)h*CCC + d] = (&acc.x)[j];
    }
}

// =================== fused CA3 recurrence (one persistent launch) ===================
__global__ void bar_reset_k(){ if (threadIdx.x < 64) g_bars[threadIdx.x] = 0; }

__device__ __forceinline__ void gbar(int slot){
    __syncthreads();
    __threadfence();
    if (threadIdx.x == 0){
        atomicAdd(&g_bars[slot], 1);
        while (atomicAdd(&g_bars[slot], 0) < GRID_REC) { }
    }
    __syncthreads();
}

// 64x64 virtual-tile GEMM step: out[b, n0+j] += over k in [kb,kb+64): X[b,k]*W[n,k]
// X read via ldcg (cross-phase data), W via __restrict__ (read-only constants).
__device__ __forceinline__ void vtile(const float* X, const float* __restrict__ W,
                                      float* out, int K, int N, int n0, int kb,
                                      float* Xs, float* Ws)
{
    const int tid = threadIdx.x;
    const int row = tid & 63, kg = tid >> 6;   // kg: 4 groups of 16 k
#pragma unroll
    for (int q=0;q<4;q++){
        float4 v = __ldcg((const float4*)(X + (size_t)row*K + kb + kg*16 + q*4));
        int kbase = kg*16 + q*4;
        Xs[(kbase+0)*72+row]=v.x; Xs[(kbase+1)*72+row]=v.y; Xs[(kbase+2)*72+row]=v.z; Xs[(kbase+3)*72+row]=v.w;
        float4 w = *(const float4*)(W + (size_t)(n0+row)*K + kb + kg*16 + q*4);
        Ws[(kbase+0)*72+row]=w.x; Ws[(kbase+1)*72+row]=w.y; Ws[(kbase+2)*72+row]=w.z; Ws[(kbase+3)*72+row]=w.w;
    }
    __syncthreads();
    const int ty = tid >> 4, tx = tid & 15;
    float acc[4][4];
#pragma unroll
    for (int i=0;i<4;i++)
#pragma unroll
        for (int j=0;j<4;j++) acc[i][j]=0.f;
#pragma unroll 8
    for (int kk=0;kk<64;kk++){
        float4 a = *(const float4*)&Xs[kk*72 + ty*4];
        float4 b = *(const float4*)&Ws[kk*72 + tx*4];
        acc[0][0]+=a.x*b.x; acc[0][1]+=a.x*b.y; acc[0][2]+=a.x*b.z; acc[0][3]+=a.x*b.w;
        acc[1][0]+=a.y*b.x; acc[1][1]+=a.y*b.y; acc[1][2]+=a.y*b.z; acc[1][3]+=a.y*b.w;
        acc[2][0]+=a.z*b.x; acc[2][1]+=a.z*b.y; acc[2][2]+=a.z*b.z; acc[2][3]+=a.z*b.w;
        acc[3][0]+=a.w*b.x; acc[3][1]+=a.w*b.y; acc[3][2]+=a.w*b.z; acc[3][3]+=a.w*b.w;
    }
    __syncthreads();
#pragma unroll
    for (int i=0;i<4;i++)
        *(float4*)(out + (size_t)(ty*4+i)*N + n0 + tx*4) =
            make_float4(acc[i][0],acc[i][1],acc[i][2],acc[i][3]);
}

__global__ __launch_bounds__(256) void rec_fused_k(
    const float* __restrict__ sepW, const float* __restrict__ sepb,
    const float* __restrict__ compW, const float* __restrict__ compb,
    const float* __restrict__ recb,
    const float* __restrict__ itcW1, const float* __restrict__ itcb1,
    const float* __restrict__ itcW2, const float* __restrict__ itcb2,
    float* __restrict__ ps)
{
    __shared__ float Xs[64*72];
    __shared__ float Ws[64*72];
    const int tid = threadIdx.x;
    const int gidx = blockIdx.x*256 + tid;      // 0..32767 (grid 128x256)
    int slot = 0;

    for (int it=0; it<3; ++it){
        // A: sep gemms  (3 branches x 8 ntiles x 8 ksplits = 192 tiles)
        for (int t = blockIdx.x; t < 192; t += GRID_REC){
            int j = t >> 6, r = t & 63, nt = r & 7, ks = r >> 3;
            vtile(g_state, sepW + (size_t)j*CCC*CCC, ps + (size_t)(j*8+ks)*(BB*CCC),
                  CCC, CCC, nt*64, ks*64, Xs, Ws);
        }
        gbar(slot++);
        // B: sep combine
        {
            int idx = gidx;   // exactly BB*CCC threads
            int n = idx & (CCC-1);
            float z[3];
#pragma unroll
            for (int j=0;j<3;j++){
                float a = 0.f;
#pragma unroll
                for (int ks=0;ks<8;ks++) a += __ldcg(ps + (size_t)(j*8+ks)*(BB*CCC) + idx);
                z[j] = a + sepb[j*CCC + n];
            }
            float v = tanhf(z[0])*0.8f;
            v = (v + tanhf(z[1])*0.8f)*0.5f;
            v = (v + tanhf(z[2])*0.8f)*0.5f;
            g_sep[idx] = v;
        }
        gbar(slot++);
        // C: comp gemms
        for (int t = blockIdx.x; t < 192; t += GRID_REC){
            int j = t >> 6, r = t & 63, nt = r & 7, ks = r >> 3;
            vtile(g_sep, compW + (size_t)j*CCC*CCC, ps + (size_t)(j*8+ks)*(BB*CCC),
                  CCC, CCC, nt*64, ks*64, Xs, Ws);
        }
        gbar(slot++);
        // D: comp combine
        {
            int idx = gidx;
            int n = idx & (CCC-1);
            float z[3];
#pragma unroll
            for (int j=0;j<3;j++){
                float a = 0.f;
#pragma unroll
                for (int ks=0;ks<8;ks++) a += __ldcg(ps + (size_t)(j*8+ks)*(BB*CCC) + idx);
                z[j] = a + compb[j*CCC + n];
            }
            float v = 0.6f/(1.0f+expf(-z[0]));
            v = (v + 0.6f/(1.0f+expf(-z[1])))*0.5f;
            v = (v + 0.6f/(1.0f+expf(-z[2])))*0.5f;
            g_comp[idx] = v;
        }
        gbar(slot++);
        // E: rec gemm (8 ntiles x 8 ksplits = 64 tiles) -> slabs 0..7
        for (int t = blockIdx.x; t < 64; t += GRID_REC){
            int nt = t & 7, ks = t >> 3;
            vtile(g_comp, g_weffT, ps + (size_t)ks*(BB*CCC), CCC, CCC, nt*64, ks*64, Xs, Ws);
        }
        gbar(slot++);
        // F: rec combine (+recb elementwise, relu)
        {
            int idx = gidx;
            float a = 0.f;
#pragma unroll
            for (int ks=0;ks<8;ks++) a += __ldcg(ps + (size_t)ks*(BB*CCC) + idx);
            g_rec[idx] = fmaxf(a + recb[idx], 0.f);
        }
        gbar(slot++);
        // G: itc1 gemm (N=256: 4 ntiles x 8 ksplits = 32 tiles) -> region after slab 8
        for (int t = blockIdx.x; t < 32; t += GRID_REC){
            int nt = t & 3, ks = t >> 2;
            vtile(g_rec, itcW1, ps + (size_t)8*(BB*CCC) + (size_t)ks*(BB*256),
                  CCC, 256, nt*64, ks*64, Xs, Ws);
        }
        gbar(slot++);
        // H: itc1 combine (relu) -> g_itch
        if (gidx < BB*256){
            int idx = gidx, n = idx & 255;
            float a = 0.f;
#pragma unroll
            for (int ks=0;ks<8;ks++) a += __ldcg(ps + (size_t)8*(BB*CCC) + (size_t)ks*(BB*256) + idx);
            g_itch[idx] = fmaxf(a + itcb1[n], 0.f);
        }
        gbar(slot++);
        // I: itc2 (warp per batch row) -> g_ic
        {
            int wid = tid >> 5, lane = tid & 31;
            int b = blockIdx.x*8 + wid;
            if (b < BB){
                float s = 0.f;
#pragma unroll
                for (int e=0;e<8;e++){
                    int c = e*32 + lane;
                    s += __ldcg(&g_itch[b*256 + c]) * itcW2[c];
                }
#pragma unroll
                for (int off=16;off;off>>=1) s += __shfl_down_sync(0xffffffffu, s, off);
                if (lane==0) g_ic[b] = 1.0f/(1.0f+expf(-(s + itcb2[0])));
            }
        }
        gbar(slot++);
        // J: state update
        {
            int idx = gidx;
            float ic = __ldcg(&g_ic[idx>>9]);
            float st = __ldcg(&g_state[idx]);
            float rc = __ldcg(&g_rec[idx]);
            g_state[idx] = (1.0f-ic)*st + ic*rc;
        }
        gbar(slot++);
    }
}

extern "C" void kernel_launch(void* const* d_in, const int* in_sizes, int n_in,
                              void* d_out, int out_size)
{
    const float* x1    = (const float*)d_in[0];
    const float* ipW1  = (const float*)d_in[1];
    const float* ipb1  = (const float*)d_in[2];
    const float* ipW2  = (const float*)d_in[3];
    const float* ipb2  = (const float*)d_in[4];
    const float* encW  = (const float*)d_in[5];
    const float* encb  = (const float*)d_in[6];
    const float* gateW = (const float*)d_in[7];
    const float* gateb = (const float*)d_in[8];
    const float* ln_g  = (const float*)d_in[9];
    const float* ln_b  = (const float*)d_in[10];
    const float* mfW   = (const float*)d_in[12];
    const float* mfb   = (const float*)d_in[13];
    const float* mf_cs = (const float*)d_in[14];
    const float* recW  = (const float*)d_in[15];
    const float* recb  = (const float*)d_in[16];
    const float* sepW  = (const float*)d_in[17];
    const float* sepb  = (const float*)d_in[18];
    const float* compW = (const float*)d_in[19];
    const float* compb = (const float*)d_in[20];
    const float* itcW1 = (const float*)d_in[21];
    const float* itcb1 = (const float*)d_in[22];
    const float* itcW2 = (const float*)d_in[23];
    const float* itcb2 = (const float*)d_in[24];
    const float* opW1  = (const float*)d_in[25];
    const float* opb1  = (const float*)d_in[26];
    const float* opW2  = (const float*)d_in[27];
    const float* opb2  = (const float*)d_in[28];

    float *p_h1,*p_h,*p_pre,*p_mask,*p_sparse,*p_state,*p_oh,*p_ps;
    cudaGetSymbolAddress((void**)&p_h1, g_h1);
    cudaGetSymbolAddress((void**)&p_h,  g_h);
    cudaGetSymbolAddress((void**)&p_pre, g_pre);
    cudaGetSymbolAddress((void**)&p_mask, g_mask);
    cudaGetSymbolAddress((void**)&p_sparse, g_sparse);
    cudaGetSymbolAddress((void**)&p_state, g_state);
    cudaGetSymbolAddress((void**)&p_oh, g_oh);
    cudaGetSymbolAddress((void**)&p_ps, g_ps);

    dim3 t(256);

    // Weff (used in all 3 iterations)
    build_weff_k<<<256, t>>>(recW);

    // input projection
    gemm64<<<dim3(8,32,1), t>>>(x1,  ipW1, p_ps, 1024, 32, 2048, 0);
    combine_k<<<512, t>>>(p_ps, 32, BB*2048, 2048, ipb1, nullptr, p_h1, M_RELU);
    gemm64<<<dim3(8,32,1), t>>>(p_h1, ipW2, p_ps, 2048, 64, 2048, 0);
    combine_k<<<512, t>>>(p_ps, 32, BB*2048, 2048, ipb2, nullptr, p_h, M_NONE);

    // granule: pre + gate mask
    gemm64<<<dim3(32,8,1), t>>>(p_h, encW, p_ps, 2048, 256, 8192, 0);
    combine_k<<<2048, t>>>(p_ps, 8, BB*8192, 8192, encb, nullptr, p_pre, M_NONE);
    gemm64<<<dim3(32,16,1), t>>>(p_pre, gateW, p_ps, 8192, 512, 8192, 0);
    combine_k<<<2048, t>>>(p_ps, 16, BB*8192, 8192, gateb, nullptr, p_mask, M_MASK);

    // inhibition + sparse + LN
    mask_stats_k<<<64, t>>>();
    sparse_ln_k<<<64, t>>>(ln_g, ln_b);

    // mossy fiber + dropout
    gemm64<<<dim3(2,128,1), t>>>(p_sparse, mfW, p_ps, 8192, 64, 512, 0);
    combine_k<<<128, t>>>(p_ps, 128, BB*512, 512, mfb, mf_cs, p_state, M_MF);

    // CA3 recurrence: fused persistent kernel
    bar_reset_k<<<1, 64>>>();
    rec_fused_k<<<GRID_REC, t>>>(sepW, sepb, compW, compb, recb,
                                 itcW1, itcb1, itcW2, itcb2, p_ps);

    // output projection
    gemm64<<<dim3(8,32,1), t>>>(p_state, opW1, p_ps, 512, 16, 2048, 0);
    combine_k<<<512, t>>>(p_ps, 32, BB*2048, 2048, opb1, nullptr, p_oh, M_RELU);
    gemm64<<<dim3(4,64,1), t>>>(p_oh, opW2, p_ps, 2048, 32, 1024, 0);
    combine_k<<<256, t>>>(p_ps, 64, BB*1024, 1024, opb2, nullptr, (float*)d_out, M_NONE);
}

// round 12
// speedup vs baseline: 1.4070x; 1.0389x over previous
#include <cuda_runtime.h>
#include <cuda_bf16.h>
#include <cstdint>
#include <math.h>

#define BB  64
#define HH  2048
#define GG  8192
#define CCC 512
#define RRR 100
#define GRID_REC 128

// ---- device scratch ----
__device__ float g_h1[BB*HH];
__device__ float g_h [BB*HH];
__device__ float g_pre[BB*GG];
__device__ float g_mask[BB*GG];
__device__ float g_S[BB];
__device__ float g_sparse[BB*GG];
__device__ float g_state[BB*CCC];
__device__ float g_sep[BB*CCC];
__device__ float g_comp[BB*CCC];
__device__ float g_rec[BB*CCC];
__device__ float g_ic[BB];
__device__ float g_weffT[CCC*CCC];
__device__ float g_oh[BB*HH];
__device__ float g_ps[1<<24];   // split-K partials
__device__ int   g_bars[64];

// ---- threefry2x32 (JAX partitionable) ----
__device__ __forceinline__ unsigned tf_rotl(unsigned x,int d){ return (x<<d)|(x>>(32-d)); }
__device__ __forceinline__ bool tf_keep(int idx){
    const unsigned ks0=0u, ks1=42u, ks2=0x1BD11BDAu^0u^42u;
    unsigned x0 = 0u + ks0;
    unsigned x1 = (unsigned)idx + ks1;
#define TFR(r) { x0+=x1; x1=tf_rotl(x1,(r)); x1^=x0; }
    TFR(13) TFR(15) TFR(26) TFR(6)  x0+=ks1; x1+=ks2+1u;
    TFR(17) TFR(29) TFR(16) TFR(24) x0+=ks2; x1+=ks0+2u;
    TFR(13) TFR(15) TFR(26) TFR(6)  x0+=ks0; x1+=ks1+3u;
    TFR(17) TFR(29) TFR(16) TFR(24) x0+=ks1; x1+=ks2+4u;
    TFR(13) TFR(15) TFR(26) TFR(6)  x0+=ks2; x1+=ks0+5u;
#undef TFR
    unsigned bits = x0 ^ x1;
    float u = __uint_as_float((bits>>9)|0x3f800000u) - 1.0f;
    return u > 0.1f;
}

// ---- scalar split-K GEMM (proven) ----
#define FMA2(accv, av, bv) asm("fma.rn.f32x2 %0, %1, %2, %0;" : "+l"(accv) : "l"(av), "l"(bv))
#define DUP2(dst, w) asm("mov.b64 %0, {%1, %1};" : "=l"(dst) : "f"(w))
__global__ __launch_bounds__(256,2) void gemm64(
    const float* __restrict__ Xg, const float* __restrict__ Wg,
    float* __restrict__ ps, int K, int Kc, int N, int wzStride)
{
    __shared__ float Xs[16][72];
    __shared__ float Ws[16][260];
    const int tid = threadIdx.x;
    const int n0  = blockIdx.x * 256;
    const int kb  = blockIdx.y * Kc;
    const float* W = Wg + (size_t)blockIdx.z*(size_t)wzStride;
    float* outp = ps + (size_t)(blockIdx.z*gridDim.y + blockIdx.y)*(size_t)(BB*N);
    const int ty = tid >> 6, tx = tid & 63;
    const int xr = tid & 63, xkg = tid >> 6;
    const int wc = tid;

    unsigned long long acc[8][4];
#pragma unroll
    for (int p=0;p<8;p++)
#pragma unroll
        for (int j=0;j<4;j++) acc[p][j]=0ull;

    float4 xa = *(const float4*)(Xg + (size_t)xr*K + kb + xkg*4);
    float4 wa0 = *(const float4*)(W + (size_t)(n0+wc)*K + kb);
    float4 wa1 = *(const float4*)(W + (size_t)(n0+wc)*K + kb + 4);
    float4 wa2 = *(const float4*)(W + (size_t)(n0+wc)*K + kb + 8);
    float4 wa3 = *(const float4*)(W + (size_t)(n0+wc)*K + kb + 12);

    for (int k0 = kb; k0 < kb + Kc; k0 += 16) {
        Xs[xkg*4+0][xr]=xa.x; Xs[xkg*4+1][xr]=xa.y; Xs[xkg*4+2][xr]=xa.z; Xs[xkg*4+3][xr]=xa.w;
        Ws[ 0][wc]=wa0.x; Ws[ 1][wc]=wa0.y; Ws[ 2][wc]=wa0.z; Ws[ 3][wc]=wa0.w;
        Ws[ 4][wc]=wa1.x; Ws[ 5][wc]=wa1.y; Ws[ 6][wc]=wa1.z; Ws[ 7][wc]=wa1.w;
        Ws[ 8][wc]=wa2.x; Ws[ 9][wc]=wa2.y; Ws[10][wc]=wa2.z; Ws[11][wc]=wa2.w;
        Ws[12][wc]=wa3.x; Ws[13][wc]=wa3.y; Ws[14][wc]=wa3.z; Ws[15][wc]=wa3.w;
        __syncthreads();
        int kn = k0 + 16;
        if (kn < kb + Kc) {
            xa  = *(const float4*)(Xg + (size_t)xr*K + kn + xkg*4);
            wa0 = *(const float4*)(W + (size_t)(n0+wc)*K + kn);
            wa1 = *(const float4*)(W + (size_t)(n0+wc)*K + kn + 4);
            wa2 = *(const float4*)(W + (size_t)(n0+wc)*K + kn + 8);
            wa3 = *(const float4*)(W + (size_t)(n0+wc)*K + kn + 12);
        }
#pragma unroll
        for (int kk=0; kk<16; ++kk) {
            ulonglong2 aA = *(const ulonglong2*)&Xs[kk][ty*16];
            ulonglong2 aB = *(const ulonglong2*)&Xs[kk][ty*16+4];
            ulonglong2 aC = *(const ulonglong2*)&Xs[kk][ty*16+8];
            ulonglong2 aD = *(const ulonglong2*)&Xs[kk][ty*16+12];
            float4 wv = *(const float4*)&Ws[kk][tx*4];
            unsigned long long b0,b1,b2,b3;
            DUP2(b0,wv.x); DUP2(b1,wv.y); DUP2(b2,wv.z); DUP2(b3,wv.w);
            FMA2(acc[0][0],aA.x,b0); FMA2(acc[0][1],aA.x,b1); FMA2(acc[0][2],aA.x,b2); FMA2(acc[0][3],aA.x,b3);
            FMA2(acc[1][0],aA.y,b0); FMA2(acc[1][1],aA.y,b1); FMA2(acc[1][2],aA.y,b2); FMA2(acc[1][3],aA.y,b3);
            FMA2(acc[2][0],aB.x,b0); FMA2(acc[2][1],aB.x,b1); FMA2(acc[2][2],aB.x,b2); FMA2(acc[2][3],aB.x,b3);
            FMA2(acc[3][0],aB.y,b0); FMA2(acc[3][1],aB.y,b1); FMA2(acc[3][2],aB.y,b2); FMA2(acc[3][3],aB.y,b3);
            FMA2(acc[4][0],aC.x,b0); FMA2(acc[4][1],aC.x,b1); FMA2(acc[4][2],aC.x,b2); FMA2(acc[4][3],aC.x,b3);
            FMA2(acc[5][0],aC.y,b0); FMA2(acc[5][1],aC.y,b1); FMA2(acc[5][2],aC.y,b2); FMA2(acc[5][3],aC.y,b3);
            FMA2(acc[6][0],aD.x,b0); FMA2(acc[6][1],aD.x,b1); FMA2(acc[6][2],aD.x,b2); FMA2(acc[6][3],aD.x,b3);
            FMA2(acc[7][0],aD.y,b0); FMA2(acc[7][1],aD.y,b1); FMA2(acc[7][2],aD.y,b2); FMA2(acc[7][3],aD.y,b3);
        }
        __syncthreads();
    }
#pragma unroll
    for (int p=0;p<8;p++){
        float lo[4], hi[4];
#pragma unroll
        for (int j=0;j<4;j++)
            asm("mov.b64 {%0, %1}, %2;" : "=f"(lo[j]), "=f"(hi[j]) : "l"(acc[p][j]));
        int r0 = ty*16 + 2*p;
        *(float4*)(outp + (size_t)r0    *N + n0 + tx*4) = make_float4(lo[0],lo[1],lo[2],lo[3]);
        *(float4*)(outp + (size_t)(r0+1)*N + n0 + tx*4) = make_float4(hi[0],hi[1],hi[2],hi[3]);
    }
}

// ---- combines / elementwise ----
#define M_NONE 0
#define M_RELU 1
#define M_MASK 2
#define M_MF   3
__global__ void combine_k(const float* __restrict__ ps, int KS, int BN, int N,
                          const float* __restrict__ bias, const float* __restrict__ extra,
                          float* __restrict__ out, int mode)
{
    int idx = blockIdx.x*256 + threadIdx.x;
    if (idx >= BN) return;
    float z = 0.0f;
    for (int s=0;s<KS;s++) z += ps[(size_t)s*BN + idx];
    int n = idx % N;
    float v;
    if (bias) z += bias[n];
    if (mode==M_NONE)      v = z;
    else if (mode==M_RELU) v = fmaxf(z,0.0f);
    else if (mode==M_MASK) { float g = 1.0f/(1.0f+expf(-z)); v = (g>0.1f)?1.0f:0.0f; }
    else { float p = z*extra[n]; v = tf_keep(idx)?p:0.0f; }
    out[idx] = v;
}
__global__ void mask_stats_k()
{
    __shared__ float red[256];
    int b = blockIdx.x, tid = threadIdx.x;
    float s = 0.0f;
    for (int j=tid;j<GG;j+=256) s += g_mask[(size_t)b*GG + j];
    red[tid]=s; __syncthreads();
    for (int off=128;off;off>>=1){ if(tid<off) red[tid]+=red[tid+off]; __syncthreads(); }
    if (tid==0) g_S[b]=red[0];
}
__global__ void sparse_ln_k(const float* __restrict__ lng, const float* __restrict__ lnb)
{
    __shared__ float sv[GG];
    __shared__ float red[256];
    int b = blockIdx.x, tid = threadIdx.x;
    float tot = 0.0f;
    for (int i=0;i<BB;i++) tot += g_S[i];
    bool anyb = tot > 0.0f;
    float Sb = g_S[b];
    float lsum = 0.0f;
    for (int j=tid;j<GG;j+=256){
        float m = g_mask[(size_t)b*GG + j];
        float p = g_pre [(size_t)b*GG + j];
        if (anyb) p -= 0.1f*(Sb - m);
        float s = p*m;
        sv[j]=s; lsum+=s;
    }
    red[tid]=lsum; __syncthreads();
    for (int off=128;off;off>>=1){ if(tid<off) red[tid]+=red[tid+off]; __syncthreads(); }
    float mu = red[0]/(float)GG; __syncthreads();
    float lsq = 0.0f;
    for (int j=tid;j<GG;j+=256){ float d=sv[j]-mu; lsq+=d*d; }
    red[tid]=lsq; __syncthreads();
    for (int off=128;off;off>>=1){ if(tid<off) red[tid]+=red[tid+off]; __syncthreads(); }
    float rstd = 1.0f/sqrtf(red[0]/(float)GG + 1e-5f);
    for (int j=tid;j<GG;j+=256)
        g_sparse[(size_t)b*GG + j] = (sv[j]-mu)*rstd*lng[j] + lnb[j];
}

// ---- weff: partials over 4 c-groups (4x parallelism), then reduce ----
__global__ void build_weff_part_k(const float* __restrict__ recW, float* __restrict__ ps)
{
    int g4 = blockIdx.x*256 + threadIdx.x;     // 0..65535
    int cg = blockIdx.y;                        // 0..3
    float4 acc = make_float4(0.f,0.f,0.f,0.f);
    int c0 = cg*25;
#pragma unroll 5
    for (int c=c0;c<c0+25;c++){
        float s = 1.0f/(1.0f+0.1f*(float)c);
        float4 v = *(const float4*)(recW + (size_t)c*CCC*CCC + g4*4);
        acc.x += s*v.x; acc.y += s*v.y; acc.z += s*v.z; acc.w += s*v.w;
    }
    ((float4*)ps)[(size_t)cg*65536 + g4] = acc;
}
__global__ void weff_reduce_k(const float* __restrict__ ps)
{
    int g4 = blockIdx.x*256 + threadIdx.x;
    float4 a = ((const float4*)ps)[g4];
    float4 b = ((const float4*)ps)[65536 + g4];
    float4 c = ((const float4*)ps)[2*65536 + g4];
    float4 d = ((const float4*)ps)[3*65536 + g4];
    float4 acc = make_float4(a.x+b.x+c.x+d.x, a.y+b.y+c.y+d.y, a.z+b.z+c.z+d.z, a.w+b.w+c.w+d.w);
    int gid = g4*4;
#pragma unroll
    for (int j=0;j<4;j++){
        int dd = (gid+j) >> 9, h = (gid+j) & (CCC-1);
        g_weffT[(size_t)h*CCC + dd] = (&acc.x)[j];
    }
}

// =================== fused CA3 recurrence (one persistent launch) ===================
__global__ void bar_reset_k(){ if (threadIdx.x < 64) g_bars[threadIdx.x] = 0; }

// arrive: fence + atomicAdd; wait: volatile-load poll with nanosleep backoff
__device__ __forceinline__ void gbar(int slot){
    __syncthreads();
    if (threadIdx.x == 0){
        __threadfence();
        atomicAdd(&g_bars[slot], 1);
        while (*((volatile int*)&g_bars[slot]) < GRID_REC) { __nanosleep(64); }
        __threadfence();
    }
    __syncthreads();
}

// 64x64 virtual-tile GEMM: out[b, n0+j] = over k in [kb,kb+64): X[b,k]*W[n,k]
__device__ __forceinline__ void vtile(const float* X, const float* __restrict__ W,
                                      float* out, int K, int N, int n0, int kb,
                                      float* Xs, float* Ws)
{
    const int tid = threadIdx.x;
    const int row = tid & 63, kg = tid >> 6;
#pragma unroll
    for (int q=0;q<4;q++){
        float4 v = __ldcg((const float4*)(X + (size_t)row*K + kb + kg*16 + q*4));
        int kbase = kg*16 + q*4;
        Xs[(kbase+0)*72+row]=v.x; Xs[(kbase+1)*72+row]=v.y; Xs[(kbase+2)*72+row]=v.z; Xs[(kbase+3)*72+row]=v.w;
        float4 w = *(const float4*)(W + (size_t)(n0+row)*K + kb + kg*16 + q*4);
        Ws[(kbase+0)*72+row]=w.x; Ws[(kbase+1)*72+row]=w.y; Ws[(kbase+2)*72+row]=w.z; Ws[(kbase+3)*72+row]=w.w;
    }
    __syncthreads();
    const int ty = tid >> 4, tx = tid & 15;
    float acc[4][4];
#pragma unroll
    for (int i=0;i<4;i++)
#pragma unroll
        for (int j=0;j<4;j++) acc[i][j]=0.f;
#pragma unroll 8
    for (int kk=0;kk<64;kk++){
        float4 a = *(const float4*)&Xs[kk*72 + ty*4];
        float4 b = *(const float4*)&Ws[kk*72 + tx*4];
        acc[0][0]+=a.x*b.x; acc[0][1]+=a.x*b.y; acc[0][2]+=a.x*b.z; acc[0][3]+=a.x*b.w;
        acc[1][0]+=a.y*b.x; acc[1][1]+=a.y*b.y; acc[1][2]+=a.y*b.z; acc[1][3]+=a.y*b.w;
        acc[2][0]+=a.z*b.x; acc[2][1]+=a.z*b.y; acc[2][2]+=a.z*b.z; acc[2][3]+=a.z*b.w;
        acc[3][0]+=a.w*b.x; acc[3][1]+=a.w*b.y; acc[3][2]+=a.w*b.z; acc[3][3]+=a.w*b.w;
    }
    __syncthreads();
#pragma unroll
    for (int i=0;i<4;i++)
        *(float4*)(out + (size_t)(ty*4+i)*N + n0 + tx*4) =
            make_float4(acc[i][0],acc[i][1],acc[i][2],acc[i][3]);
}

__global__ __launch_bounds__(256) void rec_fused_k(
    const float* __restrict__ sepW, const float* __restrict__ sepb,
    const float* __restrict__ compW, const float* __restrict__ compb,
    const float* __restrict__ recb,
    const float* __restrict__ itcW1, const float* __restrict__ itcb1,
    const float* __restrict__ itcW2, const float* __restrict__ itcb2,
    float* __restrict__ ps)
{
    __shared__ float Xs[64*72];
    __shared__ float Ws[64*72];
    const int tid = threadIdx.x;
    const int gidx = blockIdx.x*256 + tid;      // 0..32767
    int slot = 0;

    for (int it=0; it<3; ++it){
        // A: sep gemms (3 branches x 8 ntiles x 8 ksplits)
        for (int t = blockIdx.x; t < 192; t += GRID_REC){
            int j = t >> 6, r = t & 63, nt = r & 7, ks = r >> 3;
            vtile(g_state, sepW + (size_t)j*CCC*CCC, ps + (size_t)(j*8+ks)*(BB*CCC),
                  CCC, CCC, nt*64, ks*64, Xs, Ws);
        }
        gbar(slot++);
        // B: sep combine
        {
            int idx = gidx;
            int n = idx & (CCC-1);
            float z[3];
#pragma unroll
            for (int j=0;j<3;j++){
                float a = 0.f;
#pragma unroll
                for (int ks=0;ks<8;ks++) a += __ldcg(ps + (size_t)(j*8+ks)*(BB*CCC) + idx);
                z[j] = a + sepb[j*CCC + n];
            }
            float v = tanhf(z[0])*0.8f;
            v = (v + tanhf(z[1])*0.8f)*0.5f;
            v = (v + tanhf(z[2])*0.8f)*0.5f;
            g_sep[idx] = v;
        }
        gbar(slot++);
        // C: comp gemms
        for (int t = blockIdx.x; t < 192; t += GRID_REC){
            int j = t >> 6, r = t & 63, nt = r & 7, ks = r >> 3;
            vtile(g_sep, compW + (size_t)j*CCC*CCC, ps + (size_t)(j*8+ks)*(BB*CCC),
                  CCC, CCC, nt*64, ks*64, Xs, Ws);
        }
        gbar(slot++);
        // D: comp combine
        {
            int idx = gidx;
            int n = idx & (CCC-1);
            float z[3];
#pragma unroll
            for (int j=0;j<3;j++){
                float a = 0.f;
#pragma unroll
                for (int ks=0;ks<8;ks++) a += __ldcg(ps + (size_t)(j*8+ks)*(BB*CCC) + idx);
                z[j] = a + compb[j*CCC + n];
            }
            float v = 0.6f/(1.0f+expf(-z[0]));
            v = (v + 0.6f/(1.0f+expf(-z[1])))*0.5f;
            v = (v + 0.6f/(1.0f+expf(-z[2])))*0.5f;
            g_comp[idx] = v;
        }
        gbar(slot++);
        // E: rec gemm (8 ntiles x 8 ksplits)
        for (int t = blockIdx.x; t < 64; t += GRID_REC){
            int nt = t & 7, ks = t >> 3;
            vtile(g_comp, g_weffT, ps + (size_t)ks*(BB*CCC), CCC, CCC, nt*64, ks*64, Xs, Ws);
        }
        gbar(slot++);
        // F: rec combine (+recb elementwise, relu)
        {
            int idx = gidx;
            float a = 0.f;
#pragma unroll
            for (int ks=0;ks<8;ks++) a += __ldcg(ps + (size_t)ks*(BB*CCC) + idx);
            g_rec[idx] = fmaxf(a + recb[idx], 0.f);
        }
        gbar(slot++);
        // G: itc1 gemm (4 ntiles x 8 ksplits)
        for (int t = blockIdx.x; t < 32; t += GRID_REC){
            int nt = t & 3, ks = t >> 2;
            vtile(g_rec, itcW1, ps + (size_t)8*(BB*CCC) + (size_t)ks*(BB*256),
                  CCC, 256, nt*64, ks*64, Xs, Ws);
        }
        gbar(slot++);
        // H+I merged: block b (<64) computes itch row b and g_ic[b]
        if (blockIdx.x < BB){
            int b = blockIdx.x, n = tid;
            float a = 0.f;
#pragma unroll
            for (int ks=0;ks<8;ks++)
                a += __ldcg(ps + (size_t)8*(BB*CCC) + (size_t)ks*(BB*256) + b*256 + n);
            float hv = fmaxf(a + itcb1[n], 0.f);
            Xs[tid] = hv * itcW2[n];
            __syncthreads();
            for (int off=128;off;off>>=1){ if (tid<off) Xs[tid]+=Xs[tid+off]; __syncthreads(); }
            if (tid==0) g_ic[b] = 1.0f/(1.0f+expf(-(Xs[0]+itcb2[0])));
        }
        gbar(slot++);
        // J: state update
        {
            int idx = gidx;
            float ic = __ldcg(&g_ic[idx>>9]);
            float st = __ldcg(&g_state[idx]);
            float rc = __ldcg(&g_rec[idx]);
            g_state[idx] = (1.0f-ic)*st + ic*rc;
        }
        gbar(slot++);
    }
}

extern "C" void kernel_launch(void* const* d_in, const int* in_sizes, int n_in,
                              void* d_out, int out_size)
{
    const float* x1    = (const float*)d_in[0];
    const float* ipW1  = (const float*)d_in[1];
    const float* ipb1  = (const float*)d_in[2];
    const float* ipW2  = (const float*)d_in[3];
    const float* ipb2  = (const float*)d_in[4];
    const float* encW  = (const float*)d_in[5];
    const float* encb  = (const float*)d_in[6];
    const float* gateW = (const float*)d_in[7];
    const float* gateb = (const float*)d_in[8];
    const float* ln_g  = (const float*)d_in[9];
    const float* ln_b  = (const float*)d_in[10];
    const float* mfW   = (const float*)d_in[12];
    const float* mfb   = (const float*)d_in[13];
    const float* mf_cs = (const float*)d_in[14];
    const float* recW  = (const float*)d_in[15];
    const float* recb  = (const float*)d_in[16];
    const float* sepW  = (const float*)d_in[17];
    const float* sepb  = (const float*)d_in[18];
    const float* compW = (const float*)d_in[19];
    const float* compb = (const float*)d_in[20];
    const float* itcW1 = (const float*)d_in[21];
    const float* itcb1 = (const float*)d_in[22];
    const float* itcW2 = (const float*)d_in[23];
    const float* itcb2 = (const float*)d_in[24];
    const float* opW1  = (const float*)d_in[25];
    const float* opb1  = (const float*)d_in[26];
    const float* opW2  = (const float*)d_in[27];
    const float* opb2  = (const float*)d_in[28];

    float *p_h1,*p_h,*p_pre,*p_mask,*p_sparse,*p_state,*p_oh,*p_ps;
    cudaGetSymbolAddress((void**)&p_h1, g_h1);
    cudaGetSymbolAddress((void**)&p_h,  g_h);
    cudaGetSymbolAddress((void**)&p_pre, g_pre);
    cudaGetSymbolAddress((void**)&p_mask, g_mask);
    cudaGetSymbolAddress((void**)&p_sparse, g_sparse);
    cudaGetSymbolAddress((void**)&p_state, g_state);
    cudaGetSymbolAddress((void**)&p_oh, g_oh);
    cudaGetSymbolAddress((void**)&p_ps, g_ps);

    dim3 t(256);

    // Weff (4-way c-split + reduce)
    build_weff_part_k<<<dim3(256,4), t>>>(recW, p_ps);
    weff_reduce_k<<<256, t>>>(p_ps);

    // input projection
    gemm64<<<dim3(8,32,1), t>>>(x1,  ipW1, p_ps, 1024, 32, 2048, 0);
    combine_k<<<512, t>>>(p_ps, 32, BB*2048, 2048, ipb1, nullptr, p_h1, M_RELU);
    gemm64<<<dim3(8,32,1), t>>>(p_h1, ipW2, p_ps, 2048, 64, 2048, 0);
    combine_k<<<512, t>>>(p_ps, 32, BB*2048, 2048, ipb2, nullptr, p_h, M_NONE);

    // granule: pre + gate mask
    gemm64<<<dim3(32,8,1), t>>>(p_h, encW, p_ps, 2048, 256, 8192, 0);
    combine_k<<<2048, t>>>(p_ps, 8, BB*8192, 8192, encb, nullptr, p_pre, M_NONE);
    gemm64<<<dim3(32,16,1), t>>>(p_pre, gateW, p_ps, 8192, 512, 8192, 0);
    combine_k<<<2048, t>>>(p_ps, 16, BB*8192, 8192, gateb, nullptr, p_mask, M_MASK);

    // inhibition + sparse + LN
    mask_stats_k<<<64, t>>>();
    sparse_ln_k<<<64, t>>>(ln_g, ln_b);

    // mossy fiber + dropout
    gemm64<<<dim3(2,128,1), t>>>(p_sparse, mfW, p_ps, 8192, 64, 512, 0);
    combine_k<<<128, t>>>(p_ps, 128, BB*512, 512, mfb, mf_cs, p_state, M_MF);

    // CA3 recurrence: fused persistent kernel
    bar_reset_k<<<1, 64>>>();
    rec_fused_k<<<GRID_REC, t>>>(sepW, sepb, compW, compb, recb,
                                 itcW1, itcb1, itcW2, itcb2, p_ps);

    // output projection
    gemm64<<<dim3(8,32,1), t>>>(p_state, opW1, p_ps, 512, 16, 2048, 0);
    combine_k<<<512, t>>>(p_ps, 32, BB*2048, 2048, opb1, nullptr, p_oh, M_RELU);
    gemm64<<<dim3(4,64,1), t>>>(p_oh, opW2, p_ps, 2048, 32, 1024, 0);
    combine_k<<<256, t>>>(p_ps, 64, BB*1024, 1024, opb2, nullptr, (float*)d_out, M_NONE);
}